// round 11
// baseline (speedup 1.0000x reference)
#include <cuda_runtime.h>
#include <cuda_fp16.h>
#include <math.h>
#include <stdint.h>

// ---- problem constants ----
#define T_TOK 4096      // B*S
#define SEQ   2048
#define BATCH 2
#define HDIM  768
#define NHEADS 12
#define HEADD 64
#define IDIM  2048
#define NEXP  8

// ---- fp32 scratch ----
__device__ __align__(128) float g_x1  [T_TOK*HDIM];
__device__ float g_cos [SEQ*32];
__device__ float g_sin [SEQ*32];
__device__ float g_lse2[T_TOK];
__device__ int   g_cnt [NEXP];
__device__ int   g_tok [NEXP*T_TOK];
__device__ float g_wt  [NEXP*T_TOK];

// ---- fp16 activations ----
__device__ __align__(128) __half g_ax  [T_TOK*HDIM];
__device__ __align__(128) __half g_qkvh[T_TOK*2304];
__device__ __align__(128) __half g_qx  [T_TOK*HDIM];   // [b,h,s,d]
__device__ __align__(128) __half g_kx  [T_TOK*HDIM];
__device__ __align__(128) __half g_vtx [T_TOK*HDIM];   // [b,h,d,s]
__device__ __align__(128) __half g_ox  [T_TOK*HDIM];
__device__ __align__(128) __half g_xg  [(size_t)NEXP*T_TOK*HDIM];
__device__ __align__(128) __half g_hg  [(size_t)NEXP*T_TOK*IDIM];

// ---- fp16 weights ([N,K] K-major; gate/up interleaved 64-row groups) ----
__device__ __align__(128) __half g_wqkv[2304*HDIM];
__device__ __align__(128) __half g_wo  [HDIM*HDIM];
__device__ __align__(128) __half g_wgu [(size_t)NEXP*2*IDIM*HDIM];
__device__ __align__(128) __half g_wdn [(size_t)NEXP*HDIM*IDIM];

// ================= helpers =================
__device__ __forceinline__ uint32_t s2u(const void* p) {
    uint32_t a;
    asm("{ .reg .u64 t; cvta.to.shared.u64 t, %1; cvt.u32.u64 %0, t; }" : "=r"(a) : "l"(p));
    return a;
}
__device__ __forceinline__ uint32_t pack2(float a, float b) {
    __half2 h2 = __halves2half2(__float2half_rn(a), __float2half_rn(b));
    return *(uint32_t*)&h2;
}

#define LDSM4(r, a) \
    asm volatile("ldmatrix.sync.aligned.m8n8.x4.shared.b16 {%0,%1,%2,%3}, [%4];" \
        : "=r"((r)[0]), "=r"((r)[1]), "=r"((r)[2]), "=r"((r)[3]) : "r"(a))
#define LDSM2(r, a) \
    asm volatile("ldmatrix.sync.aligned.m8n8.x2.shared.b16 {%0,%1}, [%2];" \
        : "=r"((r)[0]), "=r"((r)[1]) : "r"(a))
#define MMA_F16(c, a, b) \
    asm volatile("mma.sync.aligned.m16n8k16.row.col.f32.f16.f16.f32 " \
        "{%0,%1,%2,%3}, {%4,%5,%6,%7}, {%8,%9}, {%0,%1,%2,%3};" \
        : "+f"((c)[0]), "+f"((c)[1]), "+f"((c)[2]), "+f"((c)[3]) \
        : "r"((a)[0]), "r"((a)[1]), "r"((a)[2]), "r"((a)[3]), "r"((b)[0]), "r"((b)[1]))
#define CP_ASYNC16(dst, src) \
    asm volatile("cp.async.cg.shared.global [%0], [%1], 16;" :: "r"(dst), "l"(src))

// ================= weight transpose + fp16 round =================
__global__ __launch_bounds__(256) void wconv_kernel(
    const float* __restrict__ W, __half* __restrict__ oh, int K, int N,
    size_t inZ, size_t outZ, int mode, int dstOff)
{
    W  += (size_t)blockIdx.z * inZ;
    oh += (size_t)blockIdx.z * outZ;
    __shared__ float s[64][65];
    int n0 = blockIdx.x * 64, k0 = blockIdx.y * 64;
    int tid = threadIdx.x;
    int lr = tid >> 4;
    int lc = (tid & 15) * 4;
#pragma unroll
    for (int p = 0; p < 4; p++) {
        int kk = p * 16 + lr;
        float4 v = *(const float4*)(W + (size_t)(k0 + kk) * N + n0 + lc);
        s[lc + 0][kk] = v.x; s[lc + 1][kk] = v.y;
        s[lc + 2][kk] = v.z; s[lc + 3][kk] = v.w;
    }
    __syncthreads();
    int nl = tid >> 3;
    int kq = (tid & 7) * 8;
#pragma unroll
    for (int p = 0; p < 2; p++) {
        int nn = p * 32 + nl;
        int ng = n0 + nn;
        int nd = (mode == 0) ? ng : ((ng >> 6) * 128 + (ng & 63) + ((mode == 2) ? 64 : 0));
        nd += dstOff;
        __half hb[8];
#pragma unroll
        for (int j = 0; j < 8; j++) hb[j] = __float2half_rn(s[nn][kq + j]);
        *(uint4*)(oh + (size_t)nd * K + k0 + kq) = *(uint4*)hb;
    }
}

// ================= mma.sync fp16 GEMM =================
// outMode: 0 = fp32 C (+Cadd, + optional dual write C2)
//          1 = fused silu -> fp16 SO
//          2 = plain fp16 SO
//          3 = atomic scatter-combine: C[token] += w * val  (token/w from tokArr/wtArr)
#define TMMA_SMEM_PLAIN 40960
#define TMMA_SMEM_SILU  67584

__global__ __launch_bounds__(256) void tmma_kernel(
    const __half* __restrict__ A, const __half* __restrict__ B,
    float* __restrict__ C, int M, const int* __restrict__ cntArr,
    int N, int K, const float* __restrict__ Cadd,
    size_t zsA, size_t zsB, size_t zsC,
    __half* __restrict__ SO, int outMode,
    float* __restrict__ C2,
    const int* __restrict__ tokArr, const float* __restrict__ wtArr)
{
    int z = blockIdx.z;
    int m = cntArr ? cntArr[z] : M;
    int row0 = blockIdx.y * 128;
    if (row0 >= m) return;
    int col0 = blockIdx.x * 128;
    A += zsA * z; B += zsB * z;
    if (outMode == 0) C += zsC * z;
    else if (outMode != 3) SO += zsC * z;

    extern __shared__ char sm[];
    uint32_t sbase = s2u(sm);
    int tid = threadIdx.x, lane = tid & 31, wid = tid >> 5;
    int wm = wid & 1, wn = wid >> 1;

    const __half* sp[2];
    sp[0] = A + (size_t)row0 * K;
    sp[1] = B + (size_t)col0 * K;

    float acc[4][4][4];
#pragma unroll
    for (int a = 0; a < 4; a++)
#pragma unroll
        for (int b = 0; b < 4; b++)
#pragma unroll
            for (int c = 0; c < 4; c++) acc[a][b][c] = 0.f;

    int NC = K >> 5;

#define LOAD_STAGE(cc, ss) do { \
    uint32_t _db = sbase + (ss) * 20480; \
    _Pragma("unroll") \
    for (int _t = 0; _t < 2; _t++) { \
        _Pragma("unroll") \
        for (int _i = 0; _i < 2; _i++) { \
            int _idx = tid + _i * 256; \
            int _r = _idx >> 2, _ch = _idx & 3; \
            uint32_t _dst = _db + _t * 10240 + _r * 80 + _ch * 16; \
            const void* _src = sp[_t] + (size_t)_r * K + (cc) * 32 + _ch * 8; \
            CP_ASYNC16(_dst, _src); \
        } \
    } \
    asm volatile("cp.async.commit_group;"); \
} while (0)

    LOAD_STAGE(0, 0);

    for (int c = 0; c < NC; c++) {
        if (c + 1 < NC) {
            LOAD_STAGE(c + 1, (c + 1) & 1);
            asm volatile("cp.async.wait_group 1;");
        } else {
            asm volatile("cp.async.wait_group 0;");
        }
        __syncthreads();

        uint32_t db = sbase + (c & 1) * 20480;
        uint32_t aT = db, bT = db + 10240;
#pragma unroll
        for (int ks = 0; ks < 2; ks++) {
            uint32_t af[4][4], bf[4][2];
            uint32_t aoff = (uint32_t)(wm * 64 + (lane & 15)) * 80 + ks * 32 + (lane >> 4) * 16;
            uint32_t boff = (uint32_t)(wn * 32 + (lane & 7)) * 80 + ks * 32 + ((lane >> 3) & 1) * 16;
#pragma unroll
            for (int mt = 0; mt < 4; mt++)
                LDSM4(af[mt], aT + aoff + mt * 1280);
#pragma unroll
            for (int nt = 0; nt < 4; nt++)
                LDSM2(bf[nt], bT + boff + nt * 640);
#pragma unroll
            for (int mt = 0; mt < 4; mt++)
#pragma unroll
                for (int nt = 0; nt < 4; nt++)
                    MMA_F16(acc[mt][nt], af[mt], bf[nt]);
        }
        __syncthreads();
    }

    if (outMode == 1) {
        float* stg = (float*)sm;   // 128 x 132 floats
#pragma unroll
        for (int mt = 0; mt < 4; mt++) {
            int r = wm * 64 + mt * 16 + (lane >> 2);
            int cbase = wn * 32 + (lane & 3) * 2;
#pragma unroll
            for (int half = 0; half < 2; half++) {
#pragma unroll
                for (int nt = 0; nt < 4; nt++) {
                    float2 v; v.x = acc[mt][nt][half * 2 + 0]; v.y = acc[mt][nt][half * 2 + 1];
                    *(float2*)&stg[(r + half * 8) * 132 + cbase + nt * 8] = v;
                }
            }
        }
        __syncthreads();
        int lr = tid >> 4;
        int lc = (tid & 15) * 4;
        int colg = blockIdx.x * 64 + lc;
#pragma unroll
        for (int p = 0; p < 8; p++) {
            int r = p * 16 + lr;
            int gr = row0 + r;
            if (gr < m) {
                float4 gv = *(float4*)&stg[r * 132 + lc];
                float4 uv = *(float4*)&stg[r * 132 + 64 + lc];
                float f0 = gv.x / (1.f + expf(-gv.x)) * uv.x;
                float f1 = gv.y / (1.f + expf(-gv.y)) * uv.y;
                float f2 = gv.z / (1.f + expf(-gv.z)) * uv.z;
                float f3 = gv.w / (1.f + expf(-gv.w)) * uv.w;
                uint2 hv; hv.x = pack2(f0, f1); hv.y = pack2(f2, f3);
                *(uint2*)(SO + (size_t)gr * IDIM + colg) = hv;
            }
        }
        return;
    }

    if (outMode == 3) {
        int* stok = (int*)sm;
        float* swt = (float*)(sm + 512);
        if (tid < 128) {
            int rr = row0 + tid;
            if (rr < m) {
                stok[tid] = tokArr[z * T_TOK + rr];
                swt[tid]  = wtArr[z * T_TOK + rr];
            }
        }
        __syncthreads();
#pragma unroll
        for (int mt = 0; mt < 4; mt++) {
#pragma unroll
            for (int half = 0; half < 2; half++) {
                int rl = wm * 64 + mt * 16 + (lane >> 2) + half * 8;
                if (row0 + rl < m) {
                    int tok = stok[rl];
                    float w = swt[rl];
                    float* ob = C + (size_t)tok * HDIM + col0 + wn * 32 + (lane & 3) * 2;
#pragma unroll
                    for (int nt = 0; nt < 4; nt++) {
                        atomicAdd(ob + nt * 8,     w * acc[mt][nt][half * 2 + 0]);
                        atomicAdd(ob + nt * 8 + 1, w * acc[mt][nt][half * 2 + 1]);
                    }
                }
            }
        }
        return;
    }

#pragma unroll
    for (int mt = 0; mt < 4; mt++) {
        int rbase = row0 + wm * 64 + mt * 16 + (lane >> 2);
#pragma unroll
        for (int half = 0; half < 2; half++) {
            int rr = rbase + half * 8;
            if (rr < m) {
                size_t o = (size_t)rr * N + col0 + wn * 32 + (lane & 3) * 2;
#pragma unroll
                for (int nt = 0; nt < 4; nt++) {
                    float v0 = acc[mt][nt][half * 2 + 0];
                    float v1 = acc[mt][nt][half * 2 + 1];
                    size_t oo = o + nt * 8;
                    if (outMode == 2) {
                        *(uint32_t*)(SO + oo) = pack2(v0, v1);
                    } else {
                        if (Cadd) {
                            float2 ad = *(const float2*)(Cadd + oo);
                            v0 += ad.x; v1 += ad.y;
                        }
                        float2 st2; st2.x = v0; st2.y = v1;
                        *(float2*)(C + oo) = st2;
                        if (C2) *(float2*)(C2 + oo) = st2;
                    }
                }
            }
        }
    }
}

// ================= RMSNorm (pre-attention) =================
__global__ void rmsnorm_f16_kernel(const float* __restrict__ x, const float* __restrict__ w,
                                   __half* __restrict__ oh) {
    int row = blockIdx.x;
    int tid = threadIdx.x;
    if (row == 0 && tid < NEXP) g_cnt[tid] = 0;
    const float* xr = x + (size_t)row * HDIM;
    float s = 0.f;
    for (int c = tid; c < HDIM; c += 256) { float v = xr[c]; s += v * v; }
    __shared__ float red[8];
    for (int o = 16; o; o >>= 1) s += __shfl_xor_sync(0xffffffffu, s, o);
    if ((tid & 31) == 0) red[tid >> 5] = s;
    __syncthreads();
    if (tid < 8) {
        float v = red[tid];
        for (int o = 4; o; o >>= 1) v += __shfl_xor_sync(0xffu, v, o);
        if (tid == 0) red[0] = v;
    }
    __syncthreads();
    float scale = rsqrtf(red[0] / (float)HDIM + 1e-6f);
    for (int c = tid; c < HDIM; c += 256)
        oh[(size_t)row * HDIM + c] = __float2half_rn(w[c] * xr[c] * scale);
}

// ================= fused rmsnorm2 + gate + topk + gather =================
__global__ __launch_bounds__(256) void normgate_kernel(
    const float* __restrict__ ln2w, const float* __restrict__ gw)
{
    int t = blockIdx.x;
    int tid = threadIdx.x, lane = tid & 31, wid = tid >> 5;
    __shared__ __align__(16) float xs[HDIM];
    __shared__ float slog[8];
    __shared__ float red[8];
    __shared__ int bi[2], bp[2];

    const float* xr = g_x1 + (size_t)t * HDIM;
    float s = 0.f;
    for (int c = tid; c < HDIM; c += 256) { float v = xr[c]; xs[c] = v; s += v * v; }
    for (int o = 16; o; o >>= 1) s += __shfl_xor_sync(0xffffffffu, s, o);
    if (lane == 0) red[wid] = s;
    __syncthreads();
    if (tid < 8) {
        float v = red[tid];
        for (int o = 4; o; o >>= 1) v += __shfl_xor_sync(0xffu, v, o);
        if (tid == 0) red[0] = v;
    }
    __syncthreads();
    float scale = rsqrtf(red[0] / (float)HDIM + 1e-6f);
    for (int c = tid; c < HDIM; c += 256) xs[c] = ln2w[c] * xs[c] * scale;
    __syncthreads();

    // warp e computes logit e
    float acc = 0.f;
    for (int j = lane; j < HDIM; j += 32) acc += xs[j] * gw[j * 8 + wid];
    for (int o = 16; o; o >>= 1) acc += __shfl_xor_sync(0xffffffffu, acc, o);
    if (lane == 0) slog[wid] = acc;
    __syncthreads();

    if (tid == 0) {
        float l[8];
#pragma unroll
        for (int e = 0; e < 8; e++) l[e] = slog[e];
        float mx = l[0];
#pragma unroll
        for (int e = 1; e < 8; e++) mx = fmaxf(mx, l[e]);
        float se = 0.f;
#pragma unroll
        for (int e = 0; e < 8; e++) se += expf(l[e] - mx);
        float lse = mx + logf(se);
        g_lse2[t] = lse * lse;
        int i0 = 0; float v0 = l[0];
#pragma unroll
        for (int e = 1; e < 8; e++) if (l[e] > v0) { v0 = l[e]; i0 = e; }
        int i1 = -1; float v1 = -INFINITY;
#pragma unroll
        for (int e = 0; e < 8; e++) if (e != i0 && l[e] > v1) { v1 = l[e]; i1 = e; }
        float w0 = 1.f / (1.f + expf(v1 - v0));
        float w1 = 1.f - w0;
        int p0 = atomicAdd(&g_cnt[i0], 1);
        int p1 = atomicAdd(&g_cnt[i1], 1);
        g_tok[i0 * T_TOK + p0] = t; g_wt[i0 * T_TOK + p0] = w0;
        g_tok[i1 * T_TOK + p1] = t; g_wt[i1 * T_TOK + p1] = w1;
        bi[0] = i0; bp[0] = p0; bi[1] = i1; bp[1] = p1;
    }
    __syncthreads();

    if (tid < 192) {
        int c4 = tid * 4;
        float4 v = *(float4*)&xs[c4];
        uint2 hv; hv.x = pack2(v.x, v.y); hv.y = pack2(v.z, v.w);
        *(uint2*)(g_xg + ((size_t)bi[0] * T_TOK + bp[0]) * HDIM + c4) = hv;
        *(uint2*)(g_xg + ((size_t)bi[1] * T_TOK + bp[1]) * HDIM + c4) = hv;
    }
}

__global__ void aux_kernel(float* __restrict__ out) {
    __shared__ float red[32];
    float s = 0.f;
    for (int i = threadIdx.x; i < T_TOK; i += 1024) s += g_lse2[i];
    for (int o = 16; o; o >>= 1) s += __shfl_xor_sync(0xffffffffu, s, o);
    if ((threadIdx.x & 31) == 0) red[threadIdx.x >> 5] = s;
    __syncthreads();
    if (threadIdx.x < 32) {
        float v = red[threadIdx.x];
        for (int o = 16; o; o >>= 1) v += __shfl_xor_sync(0xffffffffu, v, o);
        if (threadIdx.x == 0) out[(size_t)T_TOK * HDIM] = 0.001f * v / (float)T_TOK;
    }
}

// ================= RoPE =================
__global__ void rope_table_kernel() {
    int idx = blockIdx.x * blockDim.x + threadIdx.x;
    if (idx >= SEQ * 32) return;
    int i = idx & 31, s = idx >> 5;
    float inv = powf(10000.0f, -(float)i / 32.0f);
    float ang = (float)s * inv;
    g_cos[idx] = cosf(ang);
    g_sin[idx] = sinf(ang);
}

__global__ void rope_kernel() {
    int s = blockIdx.x, hh = blockIdx.y, bb = blockIdx.z, d = threadIdx.x;
    int t = bb * SEQ + s;
    const __half* qkv = g_qkvh + (size_t)t * 2304;
    int col  = hh * HEADD + d;
    int pcol = hh * HEADD + (d < 32 ? d + 32 : d - 32);
    float qv = __half2float(qkv[col]);
    float kv = __half2float(qkv[768 + col]);
    __half vv = qkv[1536 + col];
    float qp = __half2float(qkv[pcol]);
    float kp = __half2float(qkv[768 + pcol]);
    float cs = g_cos[s * 32 + (d & 31)], sn = g_sin[s * 32 + (d & 31)];
    float sgn = (d < 32) ? -1.f : 1.f;
    float qr = qv * cs + sgn * qp * sn;
    float kr = kv * cs + sgn * kp * sn;
    size_t dst = (((size_t)bb * NHEADS + hh) * SEQ + s) * HEADD + d;
    g_qx[dst] = __float2half_rn(qr);
    g_kx[dst] = __float2half_rn(kr);
    size_t vdst = (((size_t)bb * NHEADS + hh) * HEADD + d) * SEQ + s;
    g_vtx[vdst] = vv;
}

// ================= tensor-core flash attention (fp16) =================
#define FROW 144
#define FTILE 9216
#define FLASH_SMEM (3*FTILE)

__global__ __launch_bounds__(128) void flashmma_kernel() {
    int qt = 31 - (int)blockIdx.x;
    int hh = blockIdx.y, bb = blockIdx.z;
    extern __shared__ char fsm[];
    uint32_t sb = s2u(fsm);
    uint32_t sQ = sb, sK = sb + FTILE, sV = sb + 2*FTILE;
    char* pS = fsm;

    int tid = threadIdx.x, lane = tid & 31, w = tid >> 5;
    size_t hb = (size_t)bb * NHEADS + hh;
    const __half* Qp = g_qx + hb * SEQ * HEADD;
    const __half* Kp = g_kx + hb * SEQ * HEADD;
    const __half* Vp = g_vtx + hb * HEADD * SEQ;

    for (int i = tid; i < 512; i += 128) {
        int r = i >> 3, ch = i & 7;
        *(uint4*)(pS + r * FROW + ch * 16) =
            *(const uint4*)(Qp + (size_t)(qt * 64 + r) * HEADD + ch * 8);
    }
    __syncthreads();

    uint32_t qf[4][4];
#pragma unroll
    for (int ks = 0; ks < 4; ks++) {
        uint32_t ao = (uint32_t)(w * 16 + (lane & 15)) * FROW + ks * 32 + (lane >> 4) * 16;
        LDSM4(qf[ks], sQ + ao);
    }

    float accO[8][4];
#pragma unroll
    for (int i = 0; i < 8; i++)
#pragma unroll
        for (int j = 0; j < 4; j++) accO[i][j] = 0.f;
    float mrow0 = -INFINITY, mrow1 = -INFINITY, lrow0 = 0.f, lrow1 = 0.f;
    const float SC = 0.125f * 1.44269504f;

    for (int kt = 0; kt <= qt; kt++) {
        __syncthreads();
        for (int i = tid; i < 512; i += 128) {
            int r = i >> 3, ch = i & 7;
            *(uint4*)(pS + FTILE + r * FROW + ch * 16) =
                *(const uint4*)(Kp + (size_t)(kt * 64 + r) * HEADD + ch * 8);
            *(uint4*)(pS + 2*FTILE + r * FROW + ch * 16) =
                *(const uint4*)(Vp + (size_t)r * SEQ + kt * 64 + ch * 8);
        }
        __syncthreads();

        float sacc[8][4];
#pragma unroll
        for (int nt = 0; nt < 8; nt++)
#pragma unroll
            for (int j = 0; j < 4; j++) sacc[nt][j] = 0.f;
#pragma unroll
        for (int ks = 0; ks < 4; ks++) {
#pragma unroll
            for (int nt = 0; nt < 8; nt++) {
                uint32_t k2[2];
                uint32_t bo = (uint32_t)(nt * 8 + (lane & 7)) * FROW + ks * 32 + ((lane >> 3) & 1) * 16;
                LDSM2(k2, sK + bo);
                MMA_F16(sacc[nt], qf[ks], k2);
            }
        }

        int grow = qt * 64 + w * 16 + (lane >> 2);
        if (kt == qt) {
#pragma unroll
            for (int nt = 0; nt < 8; nt++) {
                int cbase = kt * 64 + nt * 8 + (lane & 3) * 2;
                sacc[nt][0] = (cbase     <= grow    ) ? sacc[nt][0] * SC : -1e30f;
                sacc[nt][1] = (cbase + 1 <= grow    ) ? sacc[nt][1] * SC : -1e30f;
                sacc[nt][2] = (cbase     <= grow + 8) ? sacc[nt][2] * SC : -1e30f;
                sacc[nt][3] = (cbase + 1 <= grow + 8) ? sacc[nt][3] * SC : -1e30f;
            }
        } else {
#pragma unroll
            for (int nt = 0; nt < 8; nt++)
#pragma unroll
                for (int j = 0; j < 4; j++) sacc[nt][j] *= SC;
        }

        float mx0 = -INFINITY, mx1 = -INFINITY;
#pragma unroll
        for (int nt = 0; nt < 8; nt++) {
            mx0 = fmaxf(mx0, fmaxf(sacc[nt][0], sacc[nt][1]));
            mx1 = fmaxf(mx1, fmaxf(sacc[nt][2], sacc[nt][3]));
        }
        mx0 = fmaxf(mx0, __shfl_xor_sync(0xffffffffu, mx0, 1));
        mx0 = fmaxf(mx0, __shfl_xor_sync(0xffffffffu, mx0, 2));
        mx1 = fmaxf(mx1, __shfl_xor_sync(0xffffffffu, mx1, 1));
        mx1 = fmaxf(mx1, __shfl_xor_sync(0xffffffffu, mx1, 2));
        float mn0 = fmaxf(mrow0, mx0), mn1 = fmaxf(mrow1, mx1);
        float al0 = exp2f(mrow0 - mn0), al1 = exp2f(mrow1 - mn1);
        mrow0 = mn0; mrow1 = mn1;
#pragma unroll
        for (int nt = 0; nt < 8; nt++) {
            accO[nt][0] *= al0; accO[nt][1] *= al0;
            accO[nt][2] *= al1; accO[nt][3] *= al1;
        }
        lrow0 *= al0; lrow1 *= al1;

        float sum0 = 0.f, sum1 = 0.f;
#pragma unroll
        for (int ks = 0; ks < 4; ks++) {
            float p[2][4];
#pragma unroll
            for (int h2 = 0; h2 < 2; h2++) {
                int nt = ks * 2 + h2;
                p[h2][0] = exp2f(sacc[nt][0] - mn0);
                p[h2][1] = exp2f(sacc[nt][1] - mn0);
                p[h2][2] = exp2f(sacc[nt][2] - mn1);
                p[h2][3] = exp2f(sacc[nt][3] - mn1);
                sum0 += p[h2][0] + p[h2][1];
                sum1 += p[h2][2] + p[h2][3];
            }
            uint32_t pf[4];
            pf[0] = pack2(p[0][0], p[0][1]);
            pf[1] = pack2(p[0][2], p[0][3]);
            pf[2] = pack2(p[1][0], p[1][1]);
            pf[3] = pack2(p[1][2], p[1][3]);
#pragma unroll
            for (int ntd = 0; ntd < 8; ntd++) {
                uint32_t v2[2];
                uint32_t vo = (uint32_t)(ntd * 8 + (lane & 7)) * FROW + ks * 32 + ((lane >> 3) & 1) * 16;
                LDSM2(v2, sV + vo);
                MMA_F16(accO[ntd], pf, v2);
            }
        }
        sum0 += __shfl_xor_sync(0xffffffffu, sum0, 1);
        sum0 += __shfl_xor_sync(0xffffffffu, sum0, 2);
        sum1 += __shfl_xor_sync(0xffffffffu, sum1, 1);
        sum1 += __shfl_xor_sync(0xffffffffu, sum1, 2);
        lrow0 += sum0; lrow1 += sum1;
    }

    float inv0 = 1.f / lrow0, inv1 = 1.f / lrow1;
    int row0 = qt * 64 + w * 16 + (lane >> 2);
    size_t rb = ((size_t)bb * SEQ + row0) * HDIM + hh * HEADD + (lane & 3) * 2;
#pragma unroll
    for (int ntd = 0; ntd < 8; ntd++) {
        *(uint32_t*)(g_ox + rb + ntd * 8) = pack2(accO[ntd][0] * inv0, accO[ntd][1] * inv0);
        *(uint32_t*)(g_ox + rb + 8 * HDIM + ntd * 8) = pack2(accO[ntd][2] * inv1, accO[ntd][3] * inv1);
    }
}

// ================= launch =================
#define GSA(var, sym) do { void* _p; cudaGetSymbolAddress(&_p, sym); var = (decltype(var))_p; } while (0)

extern "C" void kernel_launch(void* const* d_in, const int* in_sizes, int n_in,
                              void* d_out, int out_size) {
    const float* hidden = (const float*)d_in[0];
    const float* wq    = (const float*)d_in[2];
    const float* wk    = (const float*)d_in[3];
    const float* wv    = (const float*)d_in[4];
    const float* wo    = (const float*)d_in[5];
    const float* ln1   = (const float*)d_in[6];
    const float* ln2   = (const float*)d_in[7];
    const float* gw    = (const float*)d_in[8];
    const float* wgate = (const float*)d_in[9];
    const float* wup   = (const float*)d_in[10];
    const float* wdown = (const float*)d_in[11];
    float* out = (float*)d_out;

    float *x1;
    int *cnt, *tok;
    float *wt;
    __half *ax, *qkvh, *ox, *xg, *hg;
    __half *wqkvp, *wop, *wgup, *wdnp;
    GSA(x1, g_x1); GSA(cnt, g_cnt); GSA(tok, g_tok); GSA(wt, g_wt);
    GSA(ax, g_ax); GSA(qkvh, g_qkvh); GSA(ox, g_ox); GSA(xg, g_xg); GSA(hg, g_hg);
    GSA(wqkvp, g_wqkv); GSA(wop, g_wo); GSA(wgup, g_wgu); GSA(wdnp, g_wdn);

    cudaFuncSetAttribute((const void*)tmma_kernel,
                         cudaFuncAttributeMaxDynamicSharedMemorySize, TMMA_SMEM_SILU);
    cudaFuncSetAttribute((const void*)flashmma_kernel,
                         cudaFuncAttributeMaxDynamicSharedMemorySize, FLASH_SMEM);

    // --- side stream + events (created once on first, uncaptured call) ---
    static cudaStream_t s1 = nullptr;
    static cudaEvent_t evFork = nullptr, evWo = nullptr, evWgu = nullptr;
    if (!s1) {
        cudaStream_t tmp = nullptr;
        if (cudaStreamCreateWithFlags(&tmp, cudaStreamNonBlocking) == cudaSuccess && tmp) {
            cudaEventCreateWithFlags(&evFork, cudaEventDisableTiming);
            cudaEventCreateWithFlags(&evWo, cudaEventDisableTiming);
            cudaEventCreateWithFlags(&evWgu, cudaEventDisableTiming);
            s1 = tmp;
        }
    }
    bool fork = (s1 != nullptr);

    if (fork) {
        cudaEventRecord(evFork, 0);
        cudaStreamWaitEvent(s1, evFork, 0);
        wconv_kernel<<<dim3(12, 12, 1), 256, 0, s1>>>(wo, wop, HDIM, HDIM, 0, 0, 0, 0);
        cudaEventRecord(evWo, s1);
        wconv_kernel<<<dim3(32, 12, NEXP), 256, 0, s1>>>(wgate, wgup, HDIM, IDIM,
                                                         (size_t)HDIM*IDIM, (size_t)2*IDIM*HDIM, 1, 0);
        wconv_kernel<<<dim3(32, 12, NEXP), 256, 0, s1>>>(wup, wgup, HDIM, IDIM,
                                                         (size_t)HDIM*IDIM, (size_t)2*IDIM*HDIM, 2, 0);
        wconv_kernel<<<dim3(12, 32, NEXP), 256, 0, s1>>>(wdown, wdnp, IDIM, HDIM,
                                                         (size_t)IDIM*HDIM, (size_t)HDIM*IDIM, 0, 0);
        cudaEventRecord(evWgu, s1);
    } else {
        wconv_kernel<<<dim3(12, 12, 1), 256>>>(wo, wop, HDIM, HDIM, 0, 0, 0, 0);
        wconv_kernel<<<dim3(32, 12, NEXP), 256>>>(wgate, wgup, HDIM, IDIM,
                                                  (size_t)HDIM*IDIM, (size_t)2*IDIM*HDIM, 1, 0);
        wconv_kernel<<<dim3(32, 12, NEXP), 256>>>(wup, wgup, HDIM, IDIM,
                                                  (size_t)HDIM*IDIM, (size_t)2*IDIM*HDIM, 2, 0);
        wconv_kernel<<<dim3(12, 32, NEXP), 256>>>(wdown, wdnp, IDIM, HDIM,
                                                  (size_t)IDIM*HDIM, (size_t)HDIM*IDIM, 0, 0);
    }

    wconv_kernel<<<dim3(12, 12, 1), 256>>>(wq, wqkvp, HDIM, HDIM, 0, 0, 0, 0);
    wconv_kernel<<<dim3(12, 12, 1), 256>>>(wk, wqkvp, HDIM, HDIM, 0, 0, 0, 768);
    wconv_kernel<<<dim3(12, 12, 1), 256>>>(wv, wqkvp, HDIM, HDIM, 0, 0, 0, 1536);

    rmsnorm_f16_kernel<<<T_TOK, 256>>>(hidden, ln1, ax);

    // QKV projection -> fp16
    tmma_kernel<<<dim3(18, 32, 1), 256, TMMA_SMEM_PLAIN>>>(ax, wqkvp, nullptr,
        T_TOK, nullptr, 2304, HDIM, nullptr, 0, 0, 0, qkvh, 2, nullptr, nullptr, nullptr);

    rope_table_kernel<<<(SEQ * 32 + 255) / 256, 256>>>();
    rope_kernel<<<dim3(SEQ, NHEADS, BATCH), 64>>>();

    flashmma_kernel<<<dim3(32, NHEADS, BATCH), 128, FLASH_SMEM>>>();

    // O projection + residual; dual-write x1 and out
    if (fork) cudaStreamWaitEvent(0, evWo, 0);
    tmma_kernel<<<dim3(6, 32, 1), 256, TMMA_SMEM_PLAIN>>>(ox, wop, x1,
        T_TOK, nullptr, HDIM, HDIM, hidden, 0, 0, 0, nullptr, 0, out, nullptr, nullptr);

    // fused rmsnorm2 + gate + topk + gather
    normgate_kernel<<<T_TOK, 256>>>(ln2, gw);
    aux_kernel<<<1, 1024>>>(out);

    // MoE
    if (fork) cudaStreamWaitEvent(0, evWgu, 0);
    tmma_kernel<<<dim3(32, 32, NEXP), 256, TMMA_SMEM_SILU>>>(xg, wgup, nullptr,
        0, cnt, 2 * IDIM, HDIM, nullptr,
        (size_t)T_TOK * HDIM, (size_t)2 * IDIM * HDIM, (size_t)T_TOK * IDIM, hg, 1,
        nullptr, nullptr, nullptr);
    // down projection with fused atomic scatter-combine into out
    tmma_kernel<<<dim3(6, 32, NEXP), 256, TMMA_SMEM_PLAIN>>>(hg, wdnp, out,
        0, cnt, HDIM, IDIM, nullptr,
        (size_t)T_TOK * IDIM, (size_t)HDIM * IDIM, 0, nullptr, 3,
        nullptr, tok, wt);
}

// round 12
// speedup vs baseline: 1.5045x; 1.5045x over previous
#include <cuda_runtime.h>
#include <cuda_fp16.h>
#include <math.h>
#include <stdint.h>

// ---- problem constants ----
#define T_TOK 4096      // B*S
#define SEQ   2048
#define BATCH 2
#define HDIM  768
#define NHEADS 12
#define HEADD 64
#define IDIM  2048
#define NEXP  8

// ---- fp32 scratch ----
__device__ __align__(128) float g_x1  [T_TOK*HDIM];
__device__ __align__(128) float g_dg  [(size_t)NEXP*T_TOK*HDIM];
__device__ float g_cos [SEQ*32];
__device__ float g_sin [SEQ*32];
__device__ float g_lse2[T_TOK];
__device__ int   g_cnt [NEXP];
__device__ int   g_ie  [2*T_TOK];
__device__ int   g_islot[2*T_TOK];
__device__ float g_iw  [2*T_TOK];

// ---- fp16 activations ----
__device__ __align__(128) __half g_ax  [T_TOK*HDIM];
__device__ __align__(128) __half g_qkvh[T_TOK*2304];
__device__ __align__(128) __half g_qx  [T_TOK*HDIM];   // [b,h,s,d]
__device__ __align__(128) __half g_kx  [T_TOK*HDIM];
__device__ __align__(128) __half g_vtx [T_TOK*HDIM];   // [b,h,d,s]
__device__ __align__(128) __half g_ox  [T_TOK*HDIM];
__device__ __align__(128) __half g_xg  [(size_t)NEXP*T_TOK*HDIM];
__device__ __align__(128) __half g_hg  [(size_t)NEXP*T_TOK*IDIM];

// ---- fp16 weights ([N,K] K-major; gate/up interleaved 64-row groups) ----
__device__ __align__(128) __half g_wqkv[2304*HDIM];
__device__ __align__(128) __half g_wo  [HDIM*HDIM];
__device__ __align__(128) __half g_wgu [(size_t)NEXP*2*IDIM*HDIM];
__device__ __align__(128) __half g_wdn [(size_t)NEXP*HDIM*IDIM];

// ================= helpers =================
__device__ __forceinline__ uint32_t s2u(const void* p) {
    uint32_t a;
    asm("{ .reg .u64 t; cvta.to.shared.u64 t, %1; cvt.u32.u64 %0, t; }" : "=r"(a) : "l"(p));
    return a;
}
__device__ __forceinline__ uint32_t pack2(float a, float b) {
    __half2 h2 = __halves2half2(__float2half_rn(a), __float2half_rn(b));
    return *(uint32_t*)&h2;
}

#define LDSM4(r, a) \
    asm volatile("ldmatrix.sync.aligned.m8n8.x4.shared.b16 {%0,%1,%2,%3}, [%4];" \
        : "=r"((r)[0]), "=r"((r)[1]), "=r"((r)[2]), "=r"((r)[3]) : "r"(a))
#define LDSM2(r, a) \
    asm volatile("ldmatrix.sync.aligned.m8n8.x2.shared.b16 {%0,%1}, [%2];" \
        : "=r"((r)[0]), "=r"((r)[1]) : "r"(a))
#define MMA_F16(c, a, b) \
    asm volatile("mma.sync.aligned.m16n8k16.row.col.f32.f16.f16.f32 " \
        "{%0,%1,%2,%3}, {%4,%5,%6,%7}, {%8,%9}, {%0,%1,%2,%3};" \
        : "+f"((c)[0]), "+f"((c)[1]), "+f"((c)[2]), "+f"((c)[3]) \
        : "r"((a)[0]), "r"((a)[1]), "r"((a)[2]), "r"((a)[3]), "r"((b)[0]), "r"((b)[1]))
#define CP_ASYNC16(dst, src) \
    asm volatile("cp.async.cg.shared.global [%0], [%1], 16;" :: "r"(dst), "l"(src))

// ================= weight transpose + fp16 round =================
__global__ __launch_bounds__(256) void wconv_kernel(
    const float* __restrict__ W, __half* __restrict__ oh, int K, int N,
    size_t inZ, size_t outZ, int mode, int dstOff)
{
    W  += (size_t)blockIdx.z * inZ;
    oh += (size_t)blockIdx.z * outZ;
    __shared__ float s[64][65];
    int n0 = blockIdx.x * 64, k0 = blockIdx.y * 64;
    int tid = threadIdx.x;
    int lr = tid >> 4;
    int lc = (tid & 15) * 4;
#pragma unroll
    for (int p = 0; p < 4; p++) {
        int kk = p * 16 + lr;
        float4 v = *(const float4*)(W + (size_t)(k0 + kk) * N + n0 + lc);
        s[lc + 0][kk] = v.x; s[lc + 1][kk] = v.y;
        s[lc + 2][kk] = v.z; s[lc + 3][kk] = v.w;
    }
    __syncthreads();
    int nl = tid >> 3;
    int kq = (tid & 7) * 8;
#pragma unroll
    for (int p = 0; p < 2; p++) {
        int nn = p * 32 + nl;
        int ng = n0 + nn;
        int nd = (mode == 0) ? ng : ((ng >> 6) * 128 + (ng & 63) + ((mode == 2) ? 64 : 0));
        nd += dstOff;
        __half hb[8];
#pragma unroll
        for (int j = 0; j < 8; j++) hb[j] = __float2half_rn(s[nn][kq + j]);
        *(uint4*)(oh + (size_t)nd * K + k0 + kq) = *(uint4*)hb;
    }
}

// ================= mma.sync fp16 GEMM (batched) =================
// outMode: 0 = fp32 C (+Cadd), 1 = fused silu -> fp16 SO, 2 = plain fp16 SO
#define TMMA_SMEM_PLAIN 61440
#define TMMA_SMEM_SILU  67584

__global__ __launch_bounds__(256) void tmma_kernel(
    const __half* __restrict__ A, const __half* __restrict__ B,
    float* __restrict__ C, int M, const int* __restrict__ cntArr,
    int N, int K, const float* __restrict__ Cadd,
    size_t zsA, size_t zsB, size_t zsC,
    __half* __restrict__ SO, int outMode)
{
    int z = blockIdx.z;
    int m = cntArr ? cntArr[z] : M;
    int row0 = blockIdx.y * 128;
    if (row0 >= m) return;
    int col0 = blockIdx.x * 128;
    A += zsA * z; B += zsB * z;
    if (outMode == 0) C += zsC * z; else SO += zsC * z;

    extern __shared__ char sm[];
    uint32_t sbase = s2u(sm);
    int tid = threadIdx.x, lane = tid & 31, wid = tid >> 5;
    int wm = wid & 1, wn = wid >> 1;

    const __half* sp[2];
    sp[0] = A + (size_t)row0 * K;
    sp[1] = B + (size_t)col0 * K;

    float acc[4][4][4];
#pragma unroll
    for (int a = 0; a < 4; a++)
#pragma unroll
        for (int b = 0; b < 4; b++)
#pragma unroll
            for (int c = 0; c < 4; c++) acc[a][b][c] = 0.f;

    int NC = K >> 5;

#define LOAD_STAGE(cc, ss) do { \
    uint32_t _db = sbase + (ss) * 20480; \
    _Pragma("unroll") \
    for (int _t = 0; _t < 2; _t++) { \
        _Pragma("unroll") \
        for (int _i = 0; _i < 2; _i++) { \
            int _idx = tid + _i * 256; \
            int _r = _idx >> 2, _ch = _idx & 3; \
            uint32_t _dst = _db + _t * 10240 + _r * 80 + _ch * 16; \
            const void* _src = sp[_t] + (size_t)_r * K + (cc) * 32 + _ch * 8; \
            CP_ASYNC16(_dst, _src); \
        } \
    } \
    asm volatile("cp.async.commit_group;"); \
} while (0)

    LOAD_STAGE(0, 0);
    if (NC > 1) LOAD_STAGE(1, 1);

    int st = 0;
    for (int c = 0; c < NC; c++) {
        if (c + 2 < NC) {
            int s2 = st + 2; if (s2 >= 3) s2 -= 3;
            LOAD_STAGE(c + 2, s2);
            asm volatile("cp.async.wait_group 2;");
        } else if (c + 1 < NC) {
            asm volatile("cp.async.wait_group 1;");
        } else {
            asm volatile("cp.async.wait_group 0;");
        }
        __syncthreads();

        uint32_t db = sbase + st * 20480;
        uint32_t aT = db, bT = db + 10240;
#pragma unroll
        for (int ks = 0; ks < 2; ks++) {
            uint32_t af[4][4], bf[4][2];
            uint32_t aoff = (uint32_t)(wm * 64 + (lane & 15)) * 80 + ks * 32 + (lane >> 4) * 16;
            uint32_t boff = (uint32_t)(wn * 32 + (lane & 7)) * 80 + ks * 32 + ((lane >> 3) & 1) * 16;
#pragma unroll
            for (int mt = 0; mt < 4; mt++)
                LDSM4(af[mt], aT + aoff + mt * 1280);
#pragma unroll
            for (int nt = 0; nt < 4; nt++)
                LDSM2(bf[nt], bT + boff + nt * 640);
#pragma unroll
            for (int mt = 0; mt < 4; mt++)
#pragma unroll
                for (int nt = 0; nt < 4; nt++)
                    MMA_F16(acc[mt][nt], af[mt], bf[nt]);
        }
        __syncthreads();
        if (++st == 3) st = 0;
    }

    if (outMode == 1) {
        float* stg = (float*)sm;   // 128 x 132 floats
#pragma unroll
        for (int mt = 0; mt < 4; mt++) {
            int r = wm * 64 + mt * 16 + (lane >> 2);
            int cbase = wn * 32 + (lane & 3) * 2;
#pragma unroll
            for (int half = 0; half < 2; half++) {
#pragma unroll
                for (int nt = 0; nt < 4; nt++) {
                    float2 v; v.x = acc[mt][nt][half * 2 + 0]; v.y = acc[mt][nt][half * 2 + 1];
                    *(float2*)&stg[(r + half * 8) * 132 + cbase + nt * 8] = v;
                }
            }
        }
        __syncthreads();
        int lr = tid >> 4;
        int lc = (tid & 15) * 4;
        int colg = blockIdx.x * 64 + lc;
#pragma unroll
        for (int p = 0; p < 8; p++) {
            int r = p * 16 + lr;
            int gr = row0 + r;
            if (gr < m) {
                float4 gv = *(float4*)&stg[r * 132 + lc];
                float4 uv = *(float4*)&stg[r * 132 + 64 + lc];
                float f0 = gv.x / (1.f + expf(-gv.x)) * uv.x;
                float f1 = gv.y / (1.f + expf(-gv.y)) * uv.y;
                float f2 = gv.z / (1.f + expf(-gv.z)) * uv.z;
                float f3 = gv.w / (1.f + expf(-gv.w)) * uv.w;
                uint2 hv; hv.x = pack2(f0, f1); hv.y = pack2(f2, f3);
                *(uint2*)(SO + (size_t)gr * IDIM + colg) = hv;
            }
        }
        return;
    }

#pragma unroll
    for (int mt = 0; mt < 4; mt++) {
        int rbase = row0 + wm * 64 + mt * 16 + (lane >> 2);
#pragma unroll
        for (int half = 0; half < 2; half++) {
            int rr = rbase + half * 8;
            if (rr < m) {
                size_t o = (size_t)rr * N + col0 + wn * 32 + (lane & 3) * 2;
#pragma unroll
                for (int nt = 0; nt < 4; nt++) {
                    float v0 = acc[mt][nt][half * 2 + 0];
                    float v1 = acc[mt][nt][half * 2 + 1];
                    size_t oo = o + nt * 8;
                    if (outMode == 2) {
                        *(uint32_t*)(SO + oo) = pack2(v0, v1);
                    } else {
                        if (Cadd) {
                            float2 ad = *(const float2*)(Cadd + oo);
                            v0 += ad.x; v1 += ad.y;
                        }
                        float2 st2; st2.x = v0; st2.y = v1;
                        *(float2*)(C + oo) = st2;
                    }
                }
            }
        }
    }
}

// ================= RMSNorm (pre-attention) =================
__global__ void rmsnorm_f16_kernel(const float* __restrict__ x, const float* __restrict__ w,
                                   __half* __restrict__ oh) {
    int row = blockIdx.x;
    int tid = threadIdx.x;
    if (row == 0 && tid < NEXP) g_cnt[tid] = 0;
    const float* xr = x + (size_t)row * HDIM;
    float s = 0.f;
    for (int c = tid; c < HDIM; c += 256) { float v = xr[c]; s += v * v; }
    __shared__ float red[8];
    for (int o = 16; o; o >>= 1) s += __shfl_xor_sync(0xffffffffu, s, o);
    if ((tid & 31) == 0) red[tid >> 5] = s;
    __syncthreads();
    if (tid < 8) {
        float v = red[tid];
        for (int o = 4; o; o >>= 1) v += __shfl_xor_sync(0xffu, v, o);
        if (tid == 0) red[0] = v;
    }
    __syncthreads();
    float scale = rsqrtf(red[0] / (float)HDIM + 1e-6f);
    for (int c = tid; c < HDIM; c += 256)
        oh[(size_t)row * HDIM + c] = __float2half_rn(w[c] * xr[c] * scale);
}

// ================= fused rmsnorm2 + gate + topk + gather =================
__global__ __launch_bounds__(256) void normgate_kernel(
    const float* __restrict__ ln2w, const float* __restrict__ gw)
{
    int t = blockIdx.x;
    int tid = threadIdx.x, lane = tid & 31, wid = tid >> 5;
    __shared__ __align__(16) float xs[HDIM];
    __shared__ float slog[8];
    __shared__ float red[8];
    __shared__ int bi[2], bp[2];

    const float* xr = g_x1 + (size_t)t * HDIM;
    float s = 0.f;
    for (int c = tid; c < HDIM; c += 256) { float v = xr[c]; xs[c] = v; s += v * v; }
    for (int o = 16; o; o >>= 1) s += __shfl_xor_sync(0xffffffffu, s, o);
    if (lane == 0) red[wid] = s;
    __syncthreads();
    if (tid < 8) {
        float v = red[tid];
        for (int o = 4; o; o >>= 1) v += __shfl_xor_sync(0xffu, v, o);
        if (tid == 0) red[0] = v;
    }
    __syncthreads();
    float scale = rsqrtf(red[0] / (float)HDIM + 1e-6f);
    for (int c = tid; c < HDIM; c += 256) xs[c] = ln2w[c] * xs[c] * scale;
    __syncthreads();

    // warp e computes logit e
    float acc = 0.f;
    for (int j = lane; j < HDIM; j += 32) acc += xs[j] * gw[j * 8 + wid];
    for (int o = 16; o; o >>= 1) acc += __shfl_xor_sync(0xffffffffu, acc, o);
    if (lane == 0) slog[wid] = acc;
    __syncthreads();

    if (tid == 0) {
        float l[8];
#pragma unroll
        for (int e = 0; e < 8; e++) l[e] = slog[e];
        float mx = l[0];
#pragma unroll
        for (int e = 1; e < 8; e++) mx = fmaxf(mx, l[e]);
        float se = 0.f;
#pragma unroll
        for (int e = 0; e < 8; e++) se += expf(l[e] - mx);
        float lse = mx + logf(se);
        g_lse2[t] = lse * lse;
        int i0 = 0; float v0 = l[0];
#pragma unroll
        for (int e = 1; e < 8; e++) if (l[e] > v0) { v0 = l[e]; i0 = e; }
        int i1 = -1; float v1 = -INFINITY;
#pragma unroll
        for (int e = 0; e < 8; e++) if (e != i0 && l[e] > v1) { v1 = l[e]; i1 = e; }
        float w0 = 1.f / (1.f + expf(v1 - v0));
        float w1 = 1.f - w0;
        int p0 = atomicAdd(&g_cnt[i0], 1);
        int p1 = atomicAdd(&g_cnt[i1], 1);
        g_ie[2*t] = i0; g_islot[2*t] = p0; g_iw[2*t] = w0;
        g_ie[2*t+1] = i1; g_islot[2*t+1] = p1; g_iw[2*t+1] = w1;
        bi[0] = i0; bp[0] = p0; bi[1] = i1; bp[1] = p1;
    }
    __syncthreads();

    if (tid < 192) {
        int c4 = tid * 4;
        float4 v = *(float4*)&xs[c4];
        uint2 hv; hv.x = pack2(v.x, v.y); hv.y = pack2(v.z, v.w);
        *(uint2*)(g_xg + ((size_t)bi[0] * T_TOK + bp[0]) * HDIM + c4) = hv;
        *(uint2*)(g_xg + ((size_t)bi[1] * T_TOK + bp[1]) * HDIM + c4) = hv;
    }
}

__global__ void aux_kernel(float* __restrict__ out) {
    __shared__ float red[32];
    float s = 0.f;
    for (int i = threadIdx.x; i < T_TOK; i += 1024) s += g_lse2[i];
    for (int o = 16; o; o >>= 1) s += __shfl_xor_sync(0xffffffffu, s, o);
    if ((threadIdx.x & 31) == 0) red[threadIdx.x >> 5] = s;
    __syncthreads();
    if (threadIdx.x < 32) {
        float v = red[threadIdx.x];
        for (int o = 16; o; o >>= 1) v += __shfl_xor_sync(0xffffffffu, v, o);
        if (threadIdx.x == 0) out[(size_t)T_TOK * HDIM] = 0.001f * v / (float)T_TOK;
    }
}

__global__ void combine_kernel(float* __restrict__ out) {
    int t = blockIdx.x;
    int i0 = g_ie[2*t], i1 = g_ie[2*t+1];
    int p0 = g_islot[2*t], p1 = g_islot[2*t+1];
    float w0 = g_iw[2*t], w1 = g_iw[2*t+1];
    const float4* d0 = (const float4*)(g_dg + ((size_t)i0 * T_TOK + p0) * HDIM);
    const float4* d1 = (const float4*)(g_dg + ((size_t)i1 * T_TOK + p1) * HDIM);
    const float4* xr = (const float4*)(g_x1 + (size_t)t * HDIM);
    float4* o = (float4*)(out + (size_t)t * HDIM);
    int c = threadIdx.x;
    float4 a = xr[c], b0 = d0[c], b1 = d1[c];
    a.x += w0 * b0.x + w1 * b1.x;
    a.y += w0 * b0.y + w1 * b1.y;
    a.z += w0 * b0.z + w1 * b1.z;
    a.w += w0 * b0.w + w1 * b1.w;
    o[c] = a;
}

// ================= RoPE =================
__global__ void rope_table_kernel() {
    int idx = blockIdx.x * blockDim.x + threadIdx.x;
    if (idx >= SEQ * 32) return;
    int i = idx & 31, s = idx >> 5;
    float inv = powf(10000.0f, -(float)i / 32.0f);
    float ang = (float)s * inv;
    g_cos[idx] = cosf(ang);
    g_sin[idx] = sinf(ang);
}

__global__ void rope_kernel() {
    int s = blockIdx.x, hh = blockIdx.y, bb = blockIdx.z, d = threadIdx.x;
    int t = bb * SEQ + s;
    const __half* qkv = g_qkvh + (size_t)t * 2304;
    int col  = hh * HEADD + d;
    int pcol = hh * HEADD + (d < 32 ? d + 32 : d - 32);
    float qv = __half2float(qkv[col]);
    float kv = __half2float(qkv[768 + col]);
    __half vv = qkv[1536 + col];
    float qp = __half2float(qkv[pcol]);
    float kp = __half2float(qkv[768 + pcol]);
    float cs = g_cos[s * 32 + (d & 31)], sn = g_sin[s * 32 + (d & 31)];
    float sgn = (d < 32) ? -1.f : 1.f;
    float qr = qv * cs + sgn * qp * sn;
    float kr = kv * cs + sgn * kp * sn;
    size_t dst = (((size_t)bb * NHEADS + hh) * SEQ + s) * HEADD + d;
    g_qx[dst] = __float2half_rn(qr);
    g_kx[dst] = __float2half_rn(kr);
    size_t vdst = (((size_t)bb * NHEADS + hh) * HEADD + d) * SEQ + s;
    g_vtx[vdst] = vv;
}

// ================= tensor-core flash attention (fp16) =================
#define FROW 144
#define FTILE 9216
#define FLASH_SMEM (3*FTILE)

__global__ __launch_bounds__(128) void flashmma_kernel() {
    int qt = 31 - (int)blockIdx.x;
    int hh = blockIdx.y, bb = blockIdx.z;
    extern __shared__ char fsm[];
    uint32_t sb = s2u(fsm);
    uint32_t sQ = sb, sK = sb + FTILE, sV = sb + 2*FTILE;
    char* pS = fsm;

    int tid = threadIdx.x, lane = tid & 31, w = tid >> 5;
    size_t hb = (size_t)bb * NHEADS + hh;
    const __half* Qp = g_qx + hb * SEQ * HEADD;
    const __half* Kp = g_kx + hb * SEQ * HEADD;
    const __half* Vp = g_vtx + hb * HEADD * SEQ;

    for (int i = tid; i < 512; i += 128) {
        int r = i >> 3, ch = i & 7;
        *(uint4*)(pS + r * FROW + ch * 16) =
            *(const uint4*)(Qp + (size_t)(qt * 64 + r) * HEADD + ch * 8);
    }
    __syncthreads();

    uint32_t qf[4][4];
#pragma unroll
    for (int ks = 0; ks < 4; ks++) {
        uint32_t ao = (uint32_t)(w * 16 + (lane & 15)) * FROW + ks * 32 + (lane >> 4) * 16;
        LDSM4(qf[ks], sQ + ao);
    }

    float accO[8][4];
#pragma unroll
    for (int i = 0; i < 8; i++)
#pragma unroll
        for (int j = 0; j < 4; j++) accO[i][j] = 0.f;
    float mrow0 = -INFINITY, mrow1 = -INFINITY, lrow0 = 0.f, lrow1 = 0.f;
    const float SC = 0.125f * 1.44269504f;

    for (int kt = 0; kt <= qt; kt++) {
        __syncthreads();
        for (int i = tid; i < 512; i += 128) {
            int r = i >> 3, ch = i & 7;
            *(uint4*)(pS + FTILE + r * FROW + ch * 16) =
                *(const uint4*)(Kp + (size_t)(kt * 64 + r) * HEADD + ch * 8);
            *(uint4*)(pS + 2*FTILE + r * FROW + ch * 16) =
                *(const uint4*)(Vp + (size_t)r * SEQ + kt * 64 + ch * 8);
        }
        __syncthreads();

        float sacc[8][4];
#pragma unroll
        for (int nt = 0; nt < 8; nt++)
#pragma unroll
            for (int j = 0; j < 4; j++) sacc[nt][j] = 0.f;
#pragma unroll
        for (int ks = 0; ks < 4; ks++) {
#pragma unroll
            for (int nt = 0; nt < 8; nt++) {
                uint32_t k2[2];
                uint32_t bo = (uint32_t)(nt * 8 + (lane & 7)) * FROW + ks * 32 + ((lane >> 3) & 1) * 16;
                LDSM2(k2, sK + bo);
                MMA_F16(sacc[nt], qf[ks], k2);
            }
        }

        int grow = qt * 64 + w * 16 + (lane >> 2);
        if (kt == qt) {
#pragma unroll
            for (int nt = 0; nt < 8; nt++) {
                int cbase = kt * 64 + nt * 8 + (lane & 3) * 2;
                sacc[nt][0] = (cbase     <= grow    ) ? sacc[nt][0] * SC : -1e30f;
                sacc[nt][1] = (cbase + 1 <= grow    ) ? sacc[nt][1] * SC : -1e30f;
                sacc[nt][2] = (cbase     <= grow + 8) ? sacc[nt][2] * SC : -1e30f;
                sacc[nt][3] = (cbase + 1 <= grow + 8) ? sacc[nt][3] * SC : -1e30f;
            }
        } else {
#pragma unroll
            for (int nt = 0; nt < 8; nt++)
#pragma unroll
                for (int j = 0; j < 4; j++) sacc[nt][j] *= SC;
        }

        float mx0 = -INFINITY, mx1 = -INFINITY;
#pragma unroll
        for (int nt = 0; nt < 8; nt++) {
            mx0 = fmaxf(mx0, fmaxf(sacc[nt][0], sacc[nt][1]));
            mx1 = fmaxf(mx1, fmaxf(sacc[nt][2], sacc[nt][3]));
        }
        mx0 = fmaxf(mx0, __shfl_xor_sync(0xffffffffu, mx0, 1));
        mx0 = fmaxf(mx0, __shfl_xor_sync(0xffffffffu, mx0, 2));
        mx1 = fmaxf(mx1, __shfl_xor_sync(0xffffffffu, mx1, 1));
        mx1 = fmaxf(mx1, __shfl_xor_sync(0xffffffffu, mx1, 2));
        float mn0 = fmaxf(mrow0, mx0), mn1 = fmaxf(mrow1, mx1);
        float al0 = exp2f(mrow0 - mn0), al1 = exp2f(mrow1 - mn1);
        mrow0 = mn0; mrow1 = mn1;
#pragma unroll
        for (int nt = 0; nt < 8; nt++) {
            accO[nt][0] *= al0; accO[nt][1] *= al0;
            accO[nt][2] *= al1; accO[nt][3] *= al1;
        }
        lrow0 *= al0; lrow1 *= al1;

        float sum0 = 0.f, sum1 = 0.f;
#pragma unroll
        for (int ks = 0; ks < 4; ks++) {
            float p[2][4];
#pragma unroll
            for (int h2 = 0; h2 < 2; h2++) {
                int nt = ks * 2 + h2;
                p[h2][0] = exp2f(sacc[nt][0] - mn0);
                p[h2][1] = exp2f(sacc[nt][1] - mn0);
                p[h2][2] = exp2f(sacc[nt][2] - mn1);
                p[h2][3] = exp2f(sacc[nt][3] - mn1);
                sum0 += p[h2][0] + p[h2][1];
                sum1 += p[h2][2] + p[h2][3];
            }
            uint32_t pf[4];
            pf[0] = pack2(p[0][0], p[0][1]);
            pf[1] = pack2(p[0][2], p[0][3]);
            pf[2] = pack2(p[1][0], p[1][1]);
            pf[3] = pack2(p[1][2], p[1][3]);
#pragma unroll
            for (int ntd = 0; ntd < 8; ntd++) {
                uint32_t v2[2];
                uint32_t vo = (uint32_t)(ntd * 8 + (lane & 7)) * FROW + ks * 32 + ((lane >> 3) & 1) * 16;
                LDSM2(v2, sV + vo);
                MMA_F16(accO[ntd], pf, v2);
            }
        }
        sum0 += __shfl_xor_sync(0xffffffffu, sum0, 1);
        sum0 += __shfl_xor_sync(0xffffffffu, sum0, 2);
        sum1 += __shfl_xor_sync(0xffffffffu, sum1, 1);
        sum1 += __shfl_xor_sync(0xffffffffu, sum1, 2);
        lrow0 += sum0; lrow1 += sum1;
    }

    float inv0 = 1.f / lrow0, inv1 = 1.f / lrow1;
    int row0 = qt * 64 + w * 16 + (lane >> 2);
    size_t rb = ((size_t)bb * SEQ + row0) * HDIM + hh * HEADD + (lane & 3) * 2;
#pragma unroll
    for (int ntd = 0; ntd < 8; ntd++) {
        *(uint32_t*)(g_ox + rb + ntd * 8) = pack2(accO[ntd][0] * inv0, accO[ntd][1] * inv0);
        *(uint32_t*)(g_ox + rb + 8 * HDIM + ntd * 8) = pack2(accO[ntd][2] * inv1, accO[ntd][3] * inv1);
    }
}

// ================= launch =================
#define GSA(var, sym) do { void* _p; cudaGetSymbolAddress(&_p, sym); var = (decltype(var))_p; } while (0)

extern "C" void kernel_launch(void* const* d_in, const int* in_sizes, int n_in,
                              void* d_out, int out_size) {
    const float* hidden = (const float*)d_in[0];
    const float* wq    = (const float*)d_in[2];
    const float* wk    = (const float*)d_in[3];
    const float* wv    = (const float*)d_in[4];
    const float* wo    = (const float*)d_in[5];
    const float* ln1   = (const float*)d_in[6];
    const float* ln2   = (const float*)d_in[7];
    const float* gw    = (const float*)d_in[8];
    const float* wgate = (const float*)d_in[9];
    const float* wup   = (const float*)d_in[10];
    const float* wdown = (const float*)d_in[11];
    float* out = (float*)d_out;

    float *x1, *dg;
    int* cnt;
    __half *ax, *qkvh, *ox, *xg, *hg;
    __half *wqkvp, *wop, *wgup, *wdnp;
    GSA(x1, g_x1); GSA(dg, g_dg); GSA(cnt, g_cnt);
    GSA(ax, g_ax); GSA(qkvh, g_qkvh); GSA(ox, g_ox); GSA(xg, g_xg); GSA(hg, g_hg);
    GSA(wqkvp, g_wqkv); GSA(wop, g_wo); GSA(wgup, g_wgu); GSA(wdnp, g_wdn);

    cudaFuncSetAttribute((const void*)tmma_kernel,
                         cudaFuncAttributeMaxDynamicSharedMemorySize, TMMA_SMEM_SILU);
    cudaFuncSetAttribute((const void*)flashmma_kernel,
                         cudaFuncAttributeMaxDynamicSharedMemorySize, FLASH_SMEM);

    // --- side stream + events (created once on first, uncaptured call) ---
    static cudaStream_t s1 = nullptr;
    static cudaEvent_t evFork = nullptr, evWo = nullptr, evWgu = nullptr;
    if (!s1) {
        cudaStream_t tmp = nullptr;
        if (cudaStreamCreateWithFlags(&tmp, cudaStreamNonBlocking) == cudaSuccess && tmp) {
            cudaEventCreateWithFlags(&evFork, cudaEventDisableTiming);
            cudaEventCreateWithFlags(&evWo, cudaEventDisableTiming);
            cudaEventCreateWithFlags(&evWgu, cudaEventDisableTiming);
            s1 = tmp;
        }
    }
    bool fork = (s1 != nullptr);

    if (fork) {
        cudaEventRecord(evFork, 0);
        cudaStreamWaitEvent(s1, evFork, 0);
        wconv_kernel<<<dim3(12, 12, 1), 256, 0, s1>>>(wo, wop, HDIM, HDIM, 0, 0, 0, 0);
        cudaEventRecord(evWo, s1);
        wconv_kernel<<<dim3(32, 12, NEXP), 256, 0, s1>>>(wgate, wgup, HDIM, IDIM,
                                                         (size_t)HDIM*IDIM, (size_t)2*IDIM*HDIM, 1, 0);
        wconv_kernel<<<dim3(32, 12, NEXP), 256, 0, s1>>>(wup, wgup, HDIM, IDIM,
                                                         (size_t)HDIM*IDIM, (size_t)2*IDIM*HDIM, 2, 0);
        wconv_kernel<<<dim3(12, 32, NEXP), 256, 0, s1>>>(wdown, wdnp, IDIM, HDIM,
                                                         (size_t)IDIM*HDIM, (size_t)HDIM*IDIM, 0, 0);
        cudaEventRecord(evWgu, s1);
    } else {
        wconv_kernel<<<dim3(12, 12, 1), 256>>>(wo, wop, HDIM, HDIM, 0, 0, 0, 0);
        wconv_kernel<<<dim3(32, 12, NEXP), 256>>>(wgate, wgup, HDIM, IDIM,
                                                  (size_t)HDIM*IDIM, (size_t)2*IDIM*HDIM, 1, 0);
        wconv_kernel<<<dim3(32, 12, NEXP), 256>>>(wup, wgup, HDIM, IDIM,
                                                  (size_t)HDIM*IDIM, (size_t)2*IDIM*HDIM, 2, 0);
        wconv_kernel<<<dim3(12, 32, NEXP), 256>>>(wdown, wdnp, IDIM, HDIM,
                                                  (size_t)IDIM*HDIM, (size_t)HDIM*IDIM, 0, 0);
    }

    wconv_kernel<<<dim3(12, 12, 1), 256>>>(wq, wqkvp, HDIM, HDIM, 0, 0, 0, 0);
    wconv_kernel<<<dim3(12, 12, 1), 256>>>(wk, wqkvp, HDIM, HDIM, 0, 0, 0, 768);
    wconv_kernel<<<dim3(12, 12, 1), 256>>>(wv, wqkvp, HDIM, HDIM, 0, 0, 0, 1536);

    rmsnorm_f16_kernel<<<T_TOK, 256>>>(hidden, ln1, ax);

    // QKV projection -> fp16
    tmma_kernel<<<dim3(18, 32, 1), 256, TMMA_SMEM_PLAIN>>>(ax, wqkvp, nullptr,
        T_TOK, nullptr, 2304, HDIM, nullptr, 0, 0, 0, qkvh, 2);

    rope_table_kernel<<<(SEQ * 32 + 255) / 256, 256>>>();
    rope_kernel<<<dim3(SEQ, NHEADS, BATCH), 64>>>();

    flashmma_kernel<<<dim3(32, NHEADS, BATCH), 128, FLASH_SMEM>>>();

    if (fork) cudaStreamWaitEvent(0, evWo, 0);
    tmma_kernel<<<dim3(6, 32, 1), 256, TMMA_SMEM_PLAIN>>>(ox, wop, x1,
        T_TOK, nullptr, HDIM, HDIM, hidden, 0, 0, 0, nullptr, 0);

    // fused rmsnorm2 + gate + topk + gather
    normgate_kernel<<<T_TOK, 256>>>(ln2, gw);
    aux_kernel<<<1, 1024>>>(out);

    if (fork) cudaStreamWaitEvent(0, evWgu, 0);
    tmma_kernel<<<dim3(32, 32, NEXP), 256, TMMA_SMEM_SILU>>>(xg, wgup, nullptr,
        0, cnt, 2 * IDIM, HDIM, nullptr,
        (size_t)T_TOK * HDIM, (size_t)2 * IDIM * HDIM, (size_t)T_TOK * IDIM, hg, 1);
    tmma_kernel<<<dim3(6, 32, NEXP), 256, TMMA_SMEM_PLAIN>>>(hg, wdnp, dg,
        0, cnt, HDIM, IDIM, nullptr,
        (size_t)T_TOK * IDIM, (size_t)HDIM * IDIM, (size_t)T_TOK * HDIM, nullptr, 0);

    combine_kernel<<<T_TOK, 192>>>(out);
}

// round 13
// speedup vs baseline: 1.5849x; 1.0535x over previous
#include <cuda_runtime.h>
#include <cuda_fp16.h>
#include <math.h>
#include <stdint.h>

// ---- problem constants ----
#define T_TOK 4096      // B*S
#define SEQ   2048
#define BATCH 2
#define HDIM  768
#define NHEADS 12
#define HEADD 64
#define IDIM  2048
#define NEXP  8

// ---- fp32 scratch ----
__device__ __align__(128) float g_x1  [T_TOK*HDIM];
__device__ __align__(128) float g_dg  [(size_t)NEXP*T_TOK*HDIM];
__device__ float g_lse2[T_TOK];
__device__ int   g_cnt [NEXP];
__device__ int   g_ie  [2*T_TOK];
__device__ int   g_islot[2*T_TOK];
__device__ float g_iw  [2*T_TOK];

// ---- fp16 activations ----
__device__ __align__(128) __half g_ax  [T_TOK*HDIM];
__device__ __align__(128) __half g_qkvh[T_TOK*2304];
__device__ __align__(128) __half g_qx  [T_TOK*HDIM];   // [b,h,s,d]
__device__ __align__(128) __half g_kx  [T_TOK*HDIM];
__device__ __align__(128) __half g_vtx [T_TOK*HDIM];   // [b,h,d,s]
__device__ __align__(128) __half g_ox  [T_TOK*HDIM];
__device__ __align__(128) __half g_xg  [(size_t)NEXP*T_TOK*HDIM];
__device__ __align__(128) __half g_hg  [(size_t)NEXP*T_TOK*IDIM];

// ---- fp16 weights ([N,K] K-major; gate/up interleaved 64-row groups) ----
__device__ __align__(128) __half g_wqkv[2304*HDIM];
__device__ __align__(128) __half g_wo  [HDIM*HDIM];
__device__ __align__(128) __half g_wgu [(size_t)NEXP*2*IDIM*HDIM];
__device__ __align__(128) __half g_wdn [(size_t)NEXP*HDIM*IDIM];

// ================= helpers =================
__device__ __forceinline__ uint32_t s2u(const void* p) {
    uint32_t a;
    asm("{ .reg .u64 t; cvta.to.shared.u64 t, %1; cvt.u32.u64 %0, t; }" : "=r"(a) : "l"(p));
    return a;
}
__device__ __forceinline__ uint32_t pack2(float a, float b) {
    __half2 h2 = __halves2half2(__float2half_rn(a), __float2half_rn(b));
    return *(uint32_t*)&h2;
}

#define LDSM4(r, a) \
    asm volatile("ldmatrix.sync.aligned.m8n8.x4.shared.b16 {%0,%1,%2,%3}, [%4];" \
        : "=r"((r)[0]), "=r"((r)[1]), "=r"((r)[2]), "=r"((r)[3]) : "r"(a))
#define LDSM2(r, a) \
    asm volatile("ldmatrix.sync.aligned.m8n8.x2.shared.b16 {%0,%1}, [%2];" \
        : "=r"((r)[0]), "=r"((r)[1]) : "r"(a))
#define MMA_F16(c, a, b) \
    asm volatile("mma.sync.aligned.m16n8k16.row.col.f32.f16.f16.f32 " \
        "{%0,%1,%2,%3}, {%4,%5,%6,%7}, {%8,%9}, {%0,%1,%2,%3};" \
        : "+f"((c)[0]), "+f"((c)[1]), "+f"((c)[2]), "+f"((c)[3]) \
        : "r"((a)[0]), "r"((a)[1]), "r"((a)[2]), "r"((a)[3]), "r"((b)[0]), "r"((b)[1]))
#define CP_ASYNC16(dst, src) \
    asm volatile("cp.async.cg.shared.global [%0], [%1], 16;" :: "r"(dst), "l"(src))

// ================= weight transpose + fp16 round =================
__global__ __launch_bounds__(256) void wconv_kernel(
    const float* __restrict__ W, __half* __restrict__ oh, int K, int N,
    size_t inZ, size_t outZ, int mode, int dstOff)
{
    W  += (size_t)blockIdx.z * inZ;
    oh += (size_t)blockIdx.z * outZ;
    __shared__ float s[64][65];
    int n0 = blockIdx.x * 64, k0 = blockIdx.y * 64;
    int tid = threadIdx.x;
    int lr = tid >> 4;
    int lc = (tid & 15) * 4;
#pragma unroll
    for (int p = 0; p < 4; p++) {
        int kk = p * 16 + lr;
        float4 v = *(const float4*)(W + (size_t)(k0 + kk) * N + n0 + lc);
        s[lc + 0][kk] = v.x; s[lc + 1][kk] = v.y;
        s[lc + 2][kk] = v.z; s[lc + 3][kk] = v.w;
    }
    __syncthreads();
    int nl = tid >> 3;
    int kq = (tid & 7) * 8;
#pragma unroll
    for (int p = 0; p < 2; p++) {
        int nn = p * 32 + nl;
        int ng = n0 + nn;
        int nd = (mode == 0) ? ng : ((ng >> 6) * 128 + (ng & 63) + ((mode == 2) ? 64 : 0));
        nd += dstOff;
        __half hb[8];
#pragma unroll
        for (int j = 0; j < 8; j++) hb[j] = __float2half_rn(s[nn][kq + j]);
        *(uint4*)(oh + (size_t)nd * K + k0 + kq) = *(uint4*)hb;
    }
}

// ================= mma.sync fp16 GEMM (batched) =================
// outMode: 0 = fp32 C (+Cadd), 1 = fused silu -> fp16 SO, 2 = plain fp16 SO
#define TMMA_SMEM_PLAIN 61440
#define TMMA_SMEM_SILU  67584

__global__ __launch_bounds__(256) void tmma_kernel(
    const __half* __restrict__ A, const __half* __restrict__ B,
    float* __restrict__ C, int M, const int* __restrict__ cntArr,
    int N, int K, const float* __restrict__ Cadd,
    size_t zsA, size_t zsB, size_t zsC,
    __half* __restrict__ SO, int outMode)
{
    int z = blockIdx.z;
    int m = cntArr ? cntArr[z] : M;
    int row0 = blockIdx.y * 128;
    if (row0 >= m) return;
    int col0 = blockIdx.x * 128;
    A += zsA * z; B += zsB * z;
    if (outMode == 0) C += zsC * z; else SO += zsC * z;

    extern __shared__ char sm[];
    uint32_t sbase = s2u(sm);
    int tid = threadIdx.x, lane = tid & 31, wid = tid >> 5;
    int wm = wid & 1, wn = wid >> 1;

    const __half* sp[2];
    sp[0] = A + (size_t)row0 * K;
    sp[1] = B + (size_t)col0 * K;

    float acc[4][4][4];
#pragma unroll
    for (int a = 0; a < 4; a++)
#pragma unroll
        for (int b = 0; b < 4; b++)
#pragma unroll
            for (int c = 0; c < 4; c++) acc[a][b][c] = 0.f;

    int NC = K >> 5;

#define LOAD_STAGE(cc, ss) do { \
    uint32_t _db = sbase + (ss) * 20480; \
    _Pragma("unroll") \
    for (int _t = 0; _t < 2; _t++) { \
        _Pragma("unroll") \
        for (int _i = 0; _i < 2; _i++) { \
            int _idx = tid + _i * 256; \
            int _r = _idx >> 2, _ch = _idx & 3; \
            uint32_t _dst = _db + _t * 10240 + _r * 80 + _ch * 16; \
            const void* _src = sp[_t] + (size_t)_r * K + (cc) * 32 + _ch * 8; \
            CP_ASYNC16(_dst, _src); \
        } \
    } \
    asm volatile("cp.async.commit_group;"); \
} while (0)

    LOAD_STAGE(0, 0);
    if (NC > 1) LOAD_STAGE(1, 1);

    int st = 0;
    for (int c = 0; c < NC; c++) {
        if (c + 2 < NC) {
            int s2 = st + 2; if (s2 >= 3) s2 -= 3;
            LOAD_STAGE(c + 2, s2);
            asm volatile("cp.async.wait_group 2;");
        } else if (c + 1 < NC) {
            asm volatile("cp.async.wait_group 1;");
        } else {
            asm volatile("cp.async.wait_group 0;");
        }
        __syncthreads();

        uint32_t db = sbase + st * 20480;
        uint32_t aT = db, bT = db + 10240;
#pragma unroll
        for (int ks = 0; ks < 2; ks++) {
            uint32_t af[4][4], bf[4][2];
            uint32_t aoff = (uint32_t)(wm * 64 + (lane & 15)) * 80 + ks * 32 + (lane >> 4) * 16;
            uint32_t boff = (uint32_t)(wn * 32 + (lane & 7)) * 80 + ks * 32 + ((lane >> 3) & 1) * 16;
#pragma unroll
            for (int mt = 0; mt < 4; mt++)
                LDSM4(af[mt], aT + aoff + mt * 1280);
#pragma unroll
            for (int nt = 0; nt < 4; nt++)
                LDSM2(bf[nt], bT + boff + nt * 640);
#pragma unroll
            for (int mt = 0; mt < 4; mt++)
#pragma unroll
                for (int nt = 0; nt < 4; nt++)
                    MMA_F16(acc[mt][nt], af[mt], bf[nt]);
        }
        __syncthreads();
        if (++st == 3) st = 0;
    }

    if (outMode == 1) {
        float* stg = (float*)sm;   // 128 x 132 floats
#pragma unroll
        for (int mt = 0; mt < 4; mt++) {
            int r = wm * 64 + mt * 16 + (lane >> 2);
            int cbase = wn * 32 + (lane & 3) * 2;
#pragma unroll
            for (int half = 0; half < 2; half++) {
#pragma unroll
                for (int nt = 0; nt < 4; nt++) {
                    float2 v; v.x = acc[mt][nt][half * 2 + 0]; v.y = acc[mt][nt][half * 2 + 1];
                    *(float2*)&stg[(r + half * 8) * 132 + cbase + nt * 8] = v;
                }
            }
        }
        __syncthreads();
        int lr = tid >> 4;
        int lc = (tid & 15) * 4;
        int colg = blockIdx.x * 64 + lc;
#pragma unroll
        for (int p = 0; p < 8; p++) {
            int r = p * 16 + lr;
            int gr = row0 + r;
            if (gr < m) {
                float4 gv = *(float4*)&stg[r * 132 + lc];
                float4 uv = *(float4*)&stg[r * 132 + 64 + lc];
                float f0 = gv.x / (1.f + expf(-gv.x)) * uv.x;
                float f1 = gv.y / (1.f + expf(-gv.y)) * uv.y;
                float f2 = gv.z / (1.f + expf(-gv.z)) * uv.z;
                float f3 = gv.w / (1.f + expf(-gv.w)) * uv.w;
                uint2 hv; hv.x = pack2(f0, f1); hv.y = pack2(f2, f3);
                *(uint2*)(SO + (size_t)gr * IDIM + colg) = hv;
            }
        }
        return;
    }

#pragma unroll
    for (int mt = 0; mt < 4; mt++) {
        int rbase = row0 + wm * 64 + mt * 16 + (lane >> 2);
#pragma unroll
        for (int half = 0; half < 2; half++) {
            int rr = rbase + half * 8;
            if (rr < m) {
                size_t o = (size_t)rr * N + col0 + wn * 32 + (lane & 3) * 2;
#pragma unroll
                for (int nt = 0; nt < 4; nt++) {
                    float v0 = acc[mt][nt][half * 2 + 0];
                    float v1 = acc[mt][nt][half * 2 + 1];
                    size_t oo = o + nt * 8;
                    if (outMode == 2) {
                        *(uint32_t*)(SO + oo) = pack2(v0, v1);
                    } else {
                        if (Cadd) {
                            float2 ad = *(const float2*)(Cadd + oo);
                            v0 += ad.x; v1 += ad.y;
                        }
                        float2 st2; st2.x = v0; st2.y = v1;
                        *(float2*)(C + oo) = st2;
                    }
                }
            }
        }
    }
}

// ================= RMSNorm (pre-attention) =================
__global__ void rmsnorm_f16_kernel(const float* __restrict__ x, const float* __restrict__ w,
                                   __half* __restrict__ oh) {
    int row = blockIdx.x;
    int tid = threadIdx.x;
    if (row == 0 && tid < NEXP) g_cnt[tid] = 0;
    const float* xr = x + (size_t)row * HDIM;
    float s = 0.f;
    for (int c = tid; c < HDIM; c += 256) { float v = xr[c]; s += v * v; }
    __shared__ float red[8];
    for (int o = 16; o; o >>= 1) s += __shfl_xor_sync(0xffffffffu, s, o);
    if ((tid & 31) == 0) red[tid >> 5] = s;
    __syncthreads();
    if (tid < 8) {
        float v = red[tid];
        for (int o = 4; o; o >>= 1) v += __shfl_xor_sync(0xffu, v, o);
        if (tid == 0) red[0] = v;
    }
    __syncthreads();
    float scale = rsqrtf(red[0] / (float)HDIM + 1e-6f);
    for (int c = tid; c < HDIM; c += 256)
        oh[(size_t)row * HDIM + c] = __float2half_rn(w[c] * xr[c] * scale);
}

// ================= fused rmsnorm2 + gate + topk + gather =================
__global__ __launch_bounds__(256) void normgate_kernel(
    const float* __restrict__ ln2w, const float* __restrict__ gw)
{
    int t = blockIdx.x;
    int tid = threadIdx.x, lane = tid & 31, wid = tid >> 5;
    __shared__ __align__(16) float xs[HDIM];
    __shared__ float slog[8];
    __shared__ float red[8];
    __shared__ int bi[2], bp[2];

    const float* xr = g_x1 + (size_t)t * HDIM;
    float s = 0.f;
    for (int c = tid; c < HDIM; c += 256) { float v = xr[c]; xs[c] = v; s += v * v; }
    for (int o = 16; o; o >>= 1) s += __shfl_xor_sync(0xffffffffu, s, o);
    if (lane == 0) red[wid] = s;
    __syncthreads();
    if (tid < 8) {
        float v = red[tid];
        for (int o = 4; o; o >>= 1) v += __shfl_xor_sync(0xffu, v, o);
        if (tid == 0) red[0] = v;
    }
    __syncthreads();
    float scale = rsqrtf(red[0] / (float)HDIM + 1e-6f);
    for (int c = tid; c < HDIM; c += 256) xs[c] = ln2w[c] * xs[c] * scale;
    __syncthreads();

    float acc = 0.f;
    for (int j = lane; j < HDIM; j += 32) acc += xs[j] * gw[j * 8 + wid];
    for (int o = 16; o; o >>= 1) acc += __shfl_xor_sync(0xffffffffu, acc, o);
    if (lane == 0) slog[wid] = acc;
    __syncthreads();

    if (tid == 0) {
        float l[8];
#pragma unroll
        for (int e = 0; e < 8; e++) l[e] = slog[e];
        float mx = l[0];
#pragma unroll
        for (int e = 1; e < 8; e++) mx = fmaxf(mx, l[e]);
        float se = 0.f;
#pragma unroll
        for (int e = 0; e < 8; e++) se += expf(l[e] - mx);
        float lse = mx + logf(se);
        g_lse2[t] = lse * lse;
        int i0 = 0; float v0 = l[0];
#pragma unroll
        for (int e = 1; e < 8; e++) if (l[e] > v0) { v0 = l[e]; i0 = e; }
        int i1 = -1; float v1 = -INFINITY;
#pragma unroll
        for (int e = 0; e < 8; e++) if (e != i0 && l[e] > v1) { v1 = l[e]; i1 = e; }
        float w0 = 1.f / (1.f + expf(v1 - v0));
        float w1 = 1.f - w0;
        int p0 = atomicAdd(&g_cnt[i0], 1);
        int p1 = atomicAdd(&g_cnt[i1], 1);
        g_ie[2*t] = i0; g_islot[2*t] = p0; g_iw[2*t] = w0;
        g_ie[2*t+1] = i1; g_islot[2*t+1] = p1; g_iw[2*t+1] = w1;
        bi[0] = i0; bp[0] = p0; bi[1] = i1; bp[1] = p1;
    }
    __syncthreads();

    if (tid < 192) {
        int c4 = tid * 4;
        float4 v = *(float4*)&xs[c4];
        uint2 hv; hv.x = pack2(v.x, v.y); hv.y = pack2(v.z, v.w);
        *(uint2*)(g_xg + ((size_t)bi[0] * T_TOK + bp[0]) * HDIM + c4) = hv;
        *(uint2*)(g_xg + ((size_t)bi[1] * T_TOK + bp[1]) * HDIM + c4) = hv;
    }
}

__global__ void aux_kernel(float* __restrict__ out) {
    __shared__ float red[32];
    float s = 0.f;
    for (int i = threadIdx.x; i < T_TOK; i += 1024) s += g_lse2[i];
    for (int o = 16; o; o >>= 1) s += __shfl_xor_sync(0xffffffffu, s, o);
    if ((threadIdx.x & 31) == 0) red[threadIdx.x >> 5] = s;
    __syncthreads();
    if (threadIdx.x < 32) {
        float v = red[threadIdx.x];
        for (int o = 16; o; o >>= 1) v += __shfl_xor_sync(0xffffffffu, v, o);
        if (threadIdx.x == 0) out[(size_t)T_TOK * HDIM] = 0.001f * v / (float)T_TOK;
    }
}

__global__ void combine_kernel(float* __restrict__ out) {
    int t = blockIdx.x;
    int i0 = g_ie[2*t], i1 = g_ie[2*t+1];
    int p0 = g_islot[2*t], p1 = g_islot[2*t+1];
    float w0 = g_iw[2*t], w1 = g_iw[2*t+1];
    const float4* d0 = (const float4*)(g_dg + ((size_t)i0 * T_TOK + p0) * HDIM);
    const float4* d1 = (const float4*)(g_dg + ((size_t)i1 * T_TOK + p1) * HDIM);
    const float4* xr = (const float4*)(g_x1 + (size_t)t * HDIM);
    float4* o = (float4*)(out + (size_t)t * HDIM);
    int c = threadIdx.x;
    float4 a = xr[c], b0 = d0[c], b1 = d1[c];
    a.x += w0 * b0.x + w1 * b1.x;
    a.y += w0 * b0.y + w1 * b1.y;
    a.z += w0 * b0.z + w1 * b1.z;
    a.w += w0 * b0.w + w1 * b1.w;
    o[c] = a;
}

// ================= RoPE (table inlined) =================
__global__ void rope_kernel() {
    int s = blockIdx.x, hh = blockIdx.y, bb = blockIdx.z, d = threadIdx.x;
    int t = bb * SEQ + s;
    const __half* qkv = g_qkvh + (size_t)t * 2304;
    int col  = hh * HEADD + d;
    int pcol = hh * HEADD + (d < 32 ? d + 32 : d - 32);
    float qv = __half2float(qkv[col]);
    float kv = __half2float(qkv[768 + col]);
    __half vv = qkv[1536 + col];
    float qp = __half2float(qkv[pcol]);
    float kp = __half2float(qkv[768 + pcol]);
    float inv = powf(10000.0f, -(float)(d & 31) / 32.0f);
    float ang = (float)s * inv;
    float cs, sn;
    sincosf(ang, &sn, &cs);
    float sgn = (d < 32) ? -1.f : 1.f;
    float qr = qv * cs + sgn * qp * sn;
    float kr = kv * cs + sgn * kp * sn;
    size_t dst = (((size_t)bb * NHEADS + hh) * SEQ + s) * HEADD + d;
    g_qx[dst] = __float2half_rn(qr);
    g_kx[dst] = __float2half_rn(kr);
    size_t vdst = (((size_t)bb * NHEADS + hh) * HEADD + d) * SEQ + s;
    g_vtx[vdst] = vv;
}

// ================= tensor-core flash attention (fp16, cp.async 2-stage) ===========
#define FROW 144
#define FTILE 9216
#define FLASH_SMEM (5*FTILE)

__global__ __launch_bounds__(128) void flashmma_kernel() {
    int qt = 31 - (int)blockIdx.x;
    int hh = blockIdx.y, bb = blockIdx.z;
    extern __shared__ char fsm[];
    uint32_t sb = s2u(fsm);
    uint32_t sQ = sb;
    char* pS = fsm;

    int tid = threadIdx.x, lane = tid & 31, w = tid >> 5;
    size_t hb = (size_t)bb * NHEADS + hh;
    const __half* Qp = g_qx + hb * SEQ * HEADD;
    const __half* Kp = g_kx + hb * SEQ * HEADD;
    const __half* Vp = g_vtx + hb * HEADD * SEQ;

    // prefetch stage loader: K tile kt -> stage ss, V tile kt -> stage ss
#define FLOAD(kt, ss) do { \
    uint32_t _kb = sb + FTILE * (1 + 2 * (ss)); \
    uint32_t _vb = _kb + FTILE; \
    for (int _i = tid; _i < 512; _i += 128) { \
        int _r = _i >> 3, _ch = _i & 7; \
        CP_ASYNC16(_kb + _r * FROW + _ch * 16, Kp + (size_t)((kt) * 64 + _r) * HEADD + _ch * 8); \
        CP_ASYNC16(_vb + _r * FROW + _ch * 16, Vp + (size_t)_r * SEQ + (kt) * 64 + _ch * 8); \
    } \
    asm volatile("cp.async.commit_group;"); \
} while (0)

    // load Q tile (plain) + first K/V (async)
    FLOAD(0, 0);
    for (int i = tid; i < 512; i += 128) {
        int r = i >> 3, ch = i & 7;
        *(uint4*)(pS + r * FROW + ch * 16) =
            *(const uint4*)(Qp + (size_t)(qt * 64 + r) * HEADD + ch * 8);
    }
    __syncthreads();

    uint32_t qf[4][4];
#pragma unroll
    for (int ks = 0; ks < 4; ks++) {
        uint32_t ao = (uint32_t)(w * 16 + (lane & 15)) * FROW + ks * 32 + (lane >> 4) * 16;
        LDSM4(qf[ks], sQ + ao);
    }

    float accO[8][4];
#pragma unroll
    for (int i = 0; i < 8; i++)
#pragma unroll
        for (int j = 0; j < 4; j++) accO[i][j] = 0.f;
    float mrow0 = -INFINITY, mrow1 = -INFINITY, lrow0 = 0.f, lrow1 = 0.f;
    const float SC = 0.125f * 1.44269504f;

    for (int kt = 0; kt <= qt; kt++) {
        __syncthreads();   // all threads done reading the stage we are about to overwrite
        if (kt < qt) {
            FLOAD(kt + 1, (kt + 1) & 1);
            asm volatile("cp.async.wait_group 1;");
        } else {
            asm volatile("cp.async.wait_group 0;");
        }
        __syncthreads();

        uint32_t sK = sb + FTILE * (1 + 2 * (kt & 1));
        uint32_t sV = sK + FTILE;

        float sacc[8][4];
#pragma unroll
        for (int nt = 0; nt < 8; nt++)
#pragma unroll
            for (int j = 0; j < 4; j++) sacc[nt][j] = 0.f;
#pragma unroll
        for (int ks = 0; ks < 4; ks++) {
#pragma unroll
            for (int nt = 0; nt < 8; nt++) {
                uint32_t k2[2];
                uint32_t bo = (uint32_t)(nt * 8 + (lane & 7)) * FROW + ks * 32 + ((lane >> 3) & 1) * 16;
                LDSM2(k2, sK + bo);
                MMA_F16(sacc[nt], qf[ks], k2);
            }
        }

        int grow = qt * 64 + w * 16 + (lane >> 2);
        if (kt == qt) {
#pragma unroll
            for (int nt = 0; nt < 8; nt++) {
                int cbase = kt * 64 + nt * 8 + (lane & 3) * 2;
                sacc[nt][0] = (cbase     <= grow    ) ? sacc[nt][0] * SC : -1e30f;
                sacc[nt][1] = (cbase + 1 <= grow    ) ? sacc[nt][1] * SC : -1e30f;
                sacc[nt][2] = (cbase     <= grow + 8) ? sacc[nt][2] * SC : -1e30f;
                sacc[nt][3] = (cbase + 1 <= grow + 8) ? sacc[nt][3] * SC : -1e30f;
            }
        } else {
#pragma unroll
            for (int nt = 0; nt < 8; nt++)
#pragma unroll
                for (int j = 0; j < 4; j++) sacc[nt][j] *= SC;
        }

        float mx0 = -INFINITY, mx1 = -INFINITY;
#pragma unroll
        for (int nt = 0; nt < 8; nt++) {
            mx0 = fmaxf(mx0, fmaxf(sacc[nt][0], sacc[nt][1]));
            mx1 = fmaxf(mx1, fmaxf(sacc[nt][2], sacc[nt][3]));
        }
        mx0 = fmaxf(mx0, __shfl_xor_sync(0xffffffffu, mx0, 1));
        mx0 = fmaxf(mx0, __shfl_xor_sync(0xffffffffu, mx0, 2));
        mx1 = fmaxf(mx1, __shfl_xor_sync(0xffffffffu, mx1, 1));
        mx1 = fmaxf(mx1, __shfl_xor_sync(0xffffffffu, mx1, 2));
        float mn0 = fmaxf(mrow0, mx0), mn1 = fmaxf(mrow1, mx1);
        float al0 = exp2f(mrow0 - mn0), al1 = exp2f(mrow1 - mn1);
        mrow0 = mn0; mrow1 = mn1;
#pragma unroll
        for (int nt = 0; nt < 8; nt++) {
            accO[nt][0] *= al0; accO[nt][1] *= al0;
            accO[nt][2] *= al1; accO[nt][3] *= al1;
        }
        lrow0 *= al0; lrow1 *= al1;

        float sum0 = 0.f, sum1 = 0.f;
#pragma unroll
        for (int ks = 0; ks < 4; ks++) {
            float p[2][4];
#pragma unroll
            for (int h2 = 0; h2 < 2; h2++) {
                int nt = ks * 2 + h2;
                p[h2][0] = exp2f(sacc[nt][0] - mn0);
                p[h2][1] = exp2f(sacc[nt][1] - mn0);
                p[h2][2] = exp2f(sacc[nt][2] - mn1);
                p[h2][3] = exp2f(sacc[nt][3] - mn1);
                sum0 += p[h2][0] + p[h2][1];
                sum1 += p[h2][2] + p[h2][3];
            }
            uint32_t pf[4];
            pf[0] = pack2(p[0][0], p[0][1]);
            pf[1] = pack2(p[0][2], p[0][3]);
            pf[2] = pack2(p[1][0], p[1][1]);
            pf[3] = pack2(p[1][2], p[1][3]);
#pragma unroll
            for (int ntd = 0; ntd < 8; ntd++) {
                uint32_t v2[2];
                uint32_t vo = (uint32_t)(ntd * 8 + (lane & 7)) * FROW + ks * 32 + ((lane >> 3) & 1) * 16;
                LDSM2(v2, sV + vo);
                MMA_F16(accO[ntd], pf, v2);
            }
        }
        sum0 += __shfl_xor_sync(0xffffffffu, sum0, 1);
        sum0 += __shfl_xor_sync(0xffffffffu, sum0, 2);
        sum1 += __shfl_xor_sync(0xffffffffu, sum1, 1);
        sum1 += __shfl_xor_sync(0xffffffffu, sum1, 2);
        lrow0 += sum0; lrow1 += sum1;
    }

    float inv0 = 1.f / lrow0, inv1 = 1.f / lrow1;
    int row0 = qt * 64 + w * 16 + (lane >> 2);
    size_t rb = ((size_t)bb * SEQ + row0) * HDIM + hh * HEADD + (lane & 3) * 2;
#pragma unroll
    for (int ntd = 0; ntd < 8; ntd++) {
        *(uint32_t*)(g_ox + rb + ntd * 8) = pack2(accO[ntd][0] * inv0, accO[ntd][1] * inv0);
        *(uint32_t*)(g_ox + rb + 8 * HDIM + ntd * 8) = pack2(accO[ntd][2] * inv1, accO[ntd][3] * inv1);
    }
}

// ================= launch =================
#define GSA(var, sym) do { void* _p; cudaGetSymbolAddress(&_p, sym); var = (decltype(var))_p; } while (0)

extern "C" void kernel_launch(void* const* d_in, const int* in_sizes, int n_in,
                              void* d_out, int out_size) {
    const float* hidden = (const float*)d_in[0];
    const float* wq    = (const float*)d_in[2];
    const float* wk    = (const float*)d_in[3];
    const float* wv    = (const float*)d_in[4];
    const float* wo    = (const float*)d_in[5];
    const float* ln1   = (const float*)d_in[6];
    const float* ln2   = (const float*)d_in[7];
    const float* gw    = (const float*)d_in[8];
    const float* wgate = (const float*)d_in[9];
    const float* wup   = (const float*)d_in[10];
    const float* wdown = (const float*)d_in[11];
    float* out = (float*)d_out;

    float *x1, *dg;
    int* cnt;
    __half *ax, *qkvh, *ox, *xg, *hg;
    __half *wqkvp, *wop, *wgup, *wdnp;
    GSA(x1, g_x1); GSA(dg, g_dg); GSA(cnt, g_cnt);
    GSA(ax, g_ax); GSA(qkvh, g_qkvh); GSA(ox, g_ox); GSA(xg, g_xg); GSA(hg, g_hg);
    GSA(wqkvp, g_wqkv); GSA(wop, g_wo); GSA(wgup, g_wgu); GSA(wdnp, g_wdn);

    cudaFuncSetAttribute((const void*)tmma_kernel,
                         cudaFuncAttributeMaxDynamicSharedMemorySize, TMMA_SMEM_SILU);
    cudaFuncSetAttribute((const void*)flashmma_kernel,
                         cudaFuncAttributeMaxDynamicSharedMemorySize, FLASH_SMEM);

    // --- side stream + events (created once on first, uncaptured call) ---
    static cudaStream_t s1 = nullptr;
    static cudaEvent_t evFork = nullptr, evWo = nullptr, evWgu = nullptr;
    if (!s1) {
        cudaStream_t tmp = nullptr;
        if (cudaStreamCreateWithFlags(&tmp, cudaStreamNonBlocking) == cudaSuccess && tmp) {
            cudaEventCreateWithFlags(&evFork, cudaEventDisableTiming);
            cudaEventCreateWithFlags(&evWo, cudaEventDisableTiming);
            cudaEventCreateWithFlags(&evWgu, cudaEventDisableTiming);
            s1 = tmp;
        }
    }
    bool fork = (s1 != nullptr);

    if (fork) {
        cudaEventRecord(evFork, 0);
        cudaStreamWaitEvent(s1, evFork, 0);
        wconv_kernel<<<dim3(12, 12, 1), 256, 0, s1>>>(wo, wop, HDIM, HDIM, 0, 0, 0, 0);
        cudaEventRecord(evWo, s1);
        wconv_kernel<<<dim3(32, 12, NEXP), 256, 0, s1>>>(wgate, wgup, HDIM, IDIM,
                                                         (size_t)HDIM*IDIM, (size_t)2*IDIM*HDIM, 1, 0);
        wconv_kernel<<<dim3(32, 12, NEXP), 256, 0, s1>>>(wup, wgup, HDIM, IDIM,
                                                         (size_t)HDIM*IDIM, (size_t)2*IDIM*HDIM, 2, 0);
        wconv_kernel<<<dim3(12, 32, NEXP), 256, 0, s1>>>(wdown, wdnp, IDIM, HDIM,
                                                         (size_t)IDIM*HDIM, (size_t)HDIM*IDIM, 0, 0);
        cudaEventRecord(evWgu, s1);
    } else {
        wconv_kernel<<<dim3(12, 12, 1), 256>>>(wo, wop, HDIM, HDIM, 0, 0, 0, 0);
        wconv_kernel<<<dim3(32, 12, NEXP), 256>>>(wgate, wgup, HDIM, IDIM,
                                                  (size_t)HDIM*IDIM, (size_t)2*IDIM*HDIM, 1, 0);
        wconv_kernel<<<dim3(32, 12, NEXP), 256>>>(wup, wgup, HDIM, IDIM,
                                                  (size_t)HDIM*IDIM, (size_t)2*IDIM*HDIM, 2, 0);
        wconv_kernel<<<dim3(12, 32, NEXP), 256>>>(wdown, wdnp, IDIM, HDIM,
                                                  (size_t)IDIM*HDIM, (size_t)HDIM*IDIM, 0, 0);
    }

    wconv_kernel<<<dim3(12, 12, 1), 256>>>(wq, wqkvp, HDIM, HDIM, 0, 0, 0, 0);
    wconv_kernel<<<dim3(12, 12, 1), 256>>>(wk, wqkvp, HDIM, HDIM, 0, 0, 0, 768);
    wconv_kernel<<<dim3(12, 12, 1), 256>>>(wv, wqkvp, HDIM, HDIM, 0, 0, 0, 1536);

    rmsnorm_f16_kernel<<<T_TOK, 256>>>(hidden, ln1, ax);

    // QKV projection -> fp16
    tmma_kernel<<<dim3(18, 32, 1), 256, TMMA_SMEM_PLAIN>>>(ax, wqkvp, nullptr,
        T_TOK, nullptr, 2304, HDIM, nullptr, 0, 0, 0, qkvh, 2);

    rope_kernel<<<dim3(SEQ, NHEADS, BATCH), 64>>>();

    flashmma_kernel<<<dim3(32, NHEADS, BATCH), 128, FLASH_SMEM>>>();

    if (fork) cudaStreamWaitEvent(0, evWo, 0);
    tmma_kernel<<<dim3(6, 32, 1), 256, TMMA_SMEM_PLAIN>>>(ox, wop, x1,
        T_TOK, nullptr, HDIM, HDIM, hidden, 0, 0, 0, nullptr, 0);

    normgate_kernel<<<T_TOK, 256>>>(ln2, gw);
    aux_kernel<<<1, 1024>>>(out);

    if (fork) cudaStreamWaitEvent(0, evWgu, 0);
    tmma_kernel<<<dim3(32, 32, NEXP), 256, TMMA_SMEM_SILU>>>(xg, wgup, nullptr,
        0, cnt, 2 * IDIM, HDIM, nullptr,
        (size_t)T_TOK * HDIM, (size_t)2 * IDIM * HDIM, (size_t)T_TOK * IDIM, hg, 1);
    tmma_kernel<<<dim3(6, 32, NEXP), 256, TMMA_SMEM_PLAIN>>>(hg, wdnp, dg,
        0, cnt, HDIM, IDIM, nullptr,
        (size_t)T_TOK * IDIM, (size_t)HDIM * IDIM, (size_t)T_TOK * HDIM, nullptr, 0);

    combine_kernel<<<T_TOK, 192>>>(out);
}

// round 14
// speedup vs baseline: 1.6001x; 1.0096x over previous
#include <cuda_runtime.h>
#include <cuda_fp16.h>
#include <math.h>
#include <stdint.h>

// ---- problem constants ----
#define T_TOK 4096      // B*S
#define SEQ   2048
#define BATCH 2
#define HDIM  768
#define NHEADS 12
#define HEADD 64
#define IDIM  2048
#define NEXP  8

// ---- fp32 scratch ----
__device__ __align__(128) float g_x1  [T_TOK*HDIM];
__device__ __align__(128) float g_dg  [(size_t)NEXP*T_TOK*HDIM];
__device__ float g_cos [SEQ*32];
__device__ float g_sin [SEQ*32];
__device__ float g_lse2[T_TOK];
__device__ int   g_cnt [NEXP];
__device__ int   g_ie  [2*T_TOK];
__device__ int   g_islot[2*T_TOK];
__device__ float g_iw  [2*T_TOK];

// ---- fp16 activations ----
__device__ __align__(128) __half g_ax  [T_TOK*HDIM];
__device__ __align__(128) __half g_qx  [T_TOK*HDIM];   // [b,h,s,d]
__device__ __align__(128) __half g_kx  [T_TOK*HDIM];
__device__ __align__(128) __half g_vtx [T_TOK*HDIM];   // [b,h,d,s]
__device__ __align__(128) __half g_ox  [T_TOK*HDIM];
__device__ __align__(128) __half g_xg  [(size_t)NEXP*T_TOK*HDIM];
__device__ __align__(128) __half g_hg  [(size_t)NEXP*T_TOK*IDIM];

// ---- fp16 weights ([N,K] K-major; gate/up interleaved 64-row groups) ----
__device__ __align__(128) __half g_wqkv[2304*HDIM];
__device__ __align__(128) __half g_wo  [HDIM*HDIM];
__device__ __align__(128) __half g_wgu [(size_t)NEXP*2*IDIM*HDIM];
__device__ __align__(128) __half g_wdn [(size_t)NEXP*HDIM*IDIM];

// ================= helpers =================
__device__ __forceinline__ uint32_t s2u(const void* p) {
    uint32_t a;
    asm("{ .reg .u64 t; cvta.to.shared.u64 t, %1; cvt.u32.u64 %0, t; }" : "=r"(a) : "l"(p));
    return a;
}
__device__ __forceinline__ uint32_t pack2(float a, float b) {
    __half2 h2 = __halves2half2(__float2half_rn(a), __float2half_rn(b));
    return *(uint32_t*)&h2;
}

#define LDSM4(r, a) \
    asm volatile("ldmatrix.sync.aligned.m8n8.x4.shared.b16 {%0,%1,%2,%3}, [%4];" \
        : "=r"((r)[0]), "=r"((r)[1]), "=r"((r)[2]), "=r"((r)[3]) : "r"(a))
#define LDSM2(r, a) \
    asm volatile("ldmatrix.sync.aligned.m8n8.x2.shared.b16 {%0,%1}, [%2];" \
        : "=r"((r)[0]), "=r"((r)[1]) : "r"(a))
#define MMA_F16(c, a, b) \
    asm volatile("mma.sync.aligned.m16n8k16.row.col.f32.f16.f16.f32 " \
        "{%0,%1,%2,%3}, {%4,%5,%6,%7}, {%8,%9}, {%0,%1,%2,%3};" \
        : "+f"((c)[0]), "+f"((c)[1]), "+f"((c)[2]), "+f"((c)[3]) \
        : "r"((a)[0]), "r"((a)[1]), "r"((a)[2]), "r"((a)[3]), "r"((b)[0]), "r"((b)[1]))
#define CP_ASYNC16(dst, src) \
    asm volatile("cp.async.cg.shared.global [%0], [%1], 16;" :: "r"(dst), "l"(src))

// ================= weight transpose + fp16 round =================
__global__ __launch_bounds__(256) void wconv_kernel(
    const float* __restrict__ W, __half* __restrict__ oh, int K, int N,
    size_t inZ, size_t outZ, int mode, int dstOff)
{
    W  += (size_t)blockIdx.z * inZ;
    oh += (size_t)blockIdx.z * outZ;
    __shared__ float s[64][65];
    int n0 = blockIdx.x * 64, k0 = blockIdx.y * 64;
    int tid = threadIdx.x;
    int lr = tid >> 4;
    int lc = (tid & 15) * 4;
#pragma unroll
    for (int p = 0; p < 4; p++) {
        int kk = p * 16 + lr;
        float4 v = *(const float4*)(W + (size_t)(k0 + kk) * N + n0 + lc);
        s[lc + 0][kk] = v.x; s[lc + 1][kk] = v.y;
        s[lc + 2][kk] = v.z; s[lc + 3][kk] = v.w;
    }
    __syncthreads();
    int nl = tid >> 3;
    int kq = (tid & 7) * 8;
#pragma unroll
    for (int p = 0; p < 2; p++) {
        int nn = p * 32 + nl;
        int ng = n0 + nn;
        int nd = (mode == 0) ? ng : ((ng >> 6) * 128 + (ng & 63) + ((mode == 2) ? 64 : 0));
        nd += dstOff;
        __half hb[8];
#pragma unroll
        for (int j = 0; j < 8; j++) hb[j] = __float2half_rn(s[nn][kq + j]);
        *(uint4*)(oh + (size_t)nd * K + k0 + kq) = *(uint4*)hb;
    }
}

// ================= mma.sync fp16 GEMM (batched) =================
// outMode: 0 = fp32 C (+Cadd), 1 = fused silu -> fp16 SO, 4 = fused RoPE/V-transpose (QKV)
#define TMMA_SMEM_PLAIN 61440
#define TMMA_SMEM_BIG   67584

__global__ __launch_bounds__(256) void tmma_kernel(
    const __half* __restrict__ A, const __half* __restrict__ B,
    float* __restrict__ C, int M, const int* __restrict__ cntArr,
    int N, int K, const float* __restrict__ Cadd,
    size_t zsA, size_t zsB, size_t zsC,
    __half* __restrict__ SO, int outMode)
{
    int z = blockIdx.z;
    int m = cntArr ? cntArr[z] : M;
    int row0 = blockIdx.y * 128;
    if (row0 >= m) return;
    int col0 = blockIdx.x * 128;
    A += zsA * z; B += zsB * z;
    if (outMode == 0) C += zsC * z; else if (outMode == 1) SO += zsC * z;

    extern __shared__ char sm[];
    uint32_t sbase = s2u(sm);
    int tid = threadIdx.x, lane = tid & 31, wid = tid >> 5;
    int wm = wid & 1, wn = wid >> 1;

    const __half* sp[2];
    sp[0] = A + (size_t)row0 * K;
    sp[1] = B + (size_t)col0 * K;

    float acc[4][4][4];
#pragma unroll
    for (int a = 0; a < 4; a++)
#pragma unroll
        for (int b = 0; b < 4; b++)
#pragma unroll
            for (int c = 0; c < 4; c++) acc[a][b][c] = 0.f;

    int NC = K >> 5;

#define LOAD_STAGE(cc, ss) do { \
    uint32_t _db = sbase + (ss) * 20480; \
    _Pragma("unroll") \
    for (int _t = 0; _t < 2; _t++) { \
        _Pragma("unroll") \
        for (int _i = 0; _i < 2; _i++) { \
            int _idx = tid + _i * 256; \
            int _r = _idx >> 2, _ch = _idx & 3; \
            uint32_t _dst = _db + _t * 10240 + _r * 80 + _ch * 16; \
            const void* _src = sp[_t] + (size_t)_r * K + (cc) * 32 + _ch * 8; \
            CP_ASYNC16(_dst, _src); \
        } \
    } \
    asm volatile("cp.async.commit_group;"); \
} while (0)

    LOAD_STAGE(0, 0);
    if (NC > 1) LOAD_STAGE(1, 1);

    int st = 0;
    for (int c = 0; c < NC; c++) {
        if (c + 2 < NC) {
            int s2 = st + 2; if (s2 >= 3) s2 -= 3;
            LOAD_STAGE(c + 2, s2);
            asm volatile("cp.async.wait_group 2;");
        } else if (c + 1 < NC) {
            asm volatile("cp.async.wait_group 1;");
        } else {
            asm volatile("cp.async.wait_group 0;");
        }
        __syncthreads();

        uint32_t db = sbase + st * 20480;
        uint32_t aT = db, bT = db + 10240;
#pragma unroll
        for (int ks = 0; ks < 2; ks++) {
            uint32_t af[4][4], bf[4][2];
            uint32_t aoff = (uint32_t)(wm * 64 + (lane & 15)) * 80 + ks * 32 + (lane >> 4) * 16;
            uint32_t boff = (uint32_t)(wn * 32 + (lane & 7)) * 80 + ks * 32 + ((lane >> 3) & 1) * 16;
#pragma unroll
            for (int mt = 0; mt < 4; mt++)
                LDSM4(af[mt], aT + aoff + mt * 1280);
#pragma unroll
            for (int nt = 0; nt < 4; nt++)
                LDSM2(bf[nt], bT + boff + nt * 640);
#pragma unroll
            for (int mt = 0; mt < 4; mt++)
#pragma unroll
                for (int nt = 0; nt < 4; nt++)
                    MMA_F16(acc[mt][nt], af[mt], bf[nt]);
        }
        __syncthreads();
        if (++st == 3) st = 0;
    }

    if (outMode == 1 || outMode == 4) {
        float* stg = (float*)sm;   // 128 x 132 floats
#pragma unroll
        for (int mt = 0; mt < 4; mt++) {
            int r = wm * 64 + mt * 16 + (lane >> 2);
            int cbase = wn * 32 + (lane & 3) * 2;
#pragma unroll
            for (int half = 0; half < 2; half++) {
#pragma unroll
                for (int nt = 0; nt < 4; nt++) {
                    float2 v; v.x = acc[mt][nt][half * 2 + 0]; v.y = acc[mt][nt][half * 2 + 1];
                    *(float2*)&stg[(r + half * 8) * 132 + cbase + nt * 8] = v;
                }
            }
        }
        __syncthreads();

        if (outMode == 1) {
            int lr = tid >> 4;
            int lc = (tid & 15) * 4;
            int colg = blockIdx.x * 64 + lc;
#pragma unroll
            for (int p = 0; p < 8; p++) {
                int r = p * 16 + lr;
                int gr = row0 + r;
                if (gr < m) {
                    float4 gv = *(float4*)&stg[r * 132 + lc];
                    float4 uv = *(float4*)&stg[r * 132 + 64 + lc];
                    float f0 = gv.x / (1.f + expf(-gv.x)) * uv.x;
                    float f1 = gv.y / (1.f + expf(-gv.y)) * uv.y;
                    float f2 = gv.z / (1.f + expf(-gv.z)) * uv.z;
                    float f3 = gv.w / (1.f + expf(-gv.w)) * uv.w;
                    uint2 hv; hv.x = pack2(f0, f1); hv.y = pack2(f2, f3);
                    *(uint2*)(SO + (size_t)gr * IDIM + colg) = hv;
                }
            }
            return;
        }

        // outMode 4: fused RoPE (q/k) / transpose (v). Tile is fully inside one part.
        int part = col0 / 768;     // 0=q, 1=k, 2=v
        if (part < 2) {
            __half* dstp = (part == 0) ? g_qx : g_kx;
            int base = col0 - part * 768;
#pragma unroll
            for (int i = 0; i < 64; i++) {
                int idx = tid + i * 256;
                int cc = idx & 127, r = idx >> 7;
                int gr = row0 + r;
                int gc = base + cc;
                int h = gc >> 6, d = gc & 63;
                int bb = gr >> 11, s = gr & 2047;
                float v = stg[r * 132 + cc];
                int pairc = cc + ((d < 32) ? 32 : -32);
                float pv = stg[r * 132 + pairc];
                float cs = g_cos[s * 32 + (d & 31)];
                float sn = g_sin[s * 32 + (d & 31)];
                float sgn = (d < 32) ? -1.f : 1.f;
                float rot = v * cs + sgn * pv * sn;
                dstp[(((size_t)bb * NHEADS + h) * SEQ + s) * HEADD + d] = __float2half_rn(rot);
            }
        } else {
            int base = col0 - 1536;
#pragma unroll
            for (int i = 0; i < 64; i++) {
                int idx = tid + i * 256;
                int r = idx & 127, cc = idx >> 7;
                int gr = row0 + r;
                int gc = base + cc;
                int h = gc >> 6, d = gc & 63;
                int bb = gr >> 11, s = gr & 2047;
                g_vtx[(((size_t)bb * NHEADS + h) * HEADD + d) * SEQ + s] =
                    __float2half_rn(stg[r * 132 + cc]);
            }
        }
        return;
    }

#pragma unroll
    for (int mt = 0; mt < 4; mt++) {
        int rbase = row0 + wm * 64 + mt * 16 + (lane >> 2);
#pragma unroll
        for (int half = 0; half < 2; half++) {
            int rr = rbase + half * 8;
            if (rr < m) {
                size_t o = (size_t)rr * N + col0 + wn * 32 + (lane & 3) * 2;
#pragma unroll
                for (int nt = 0; nt < 4; nt++) {
                    float v0 = acc[mt][nt][half * 2 + 0];
                    float v1 = acc[mt][nt][half * 2 + 1];
                    size_t oo = o + nt * 8;
                    if (Cadd) {
                        float2 ad = *(const float2*)(Cadd + oo);
                        v0 += ad.x; v1 += ad.y;
                    }
                    float2 st2; st2.x = v0; st2.y = v1;
                    *(float2*)(C + oo) = st2;
                }
            }
        }
    }
}

// ================= RMSNorm (pre-attention) + rope table fill =================
__global__ void rmsnorm_f16_kernel(const float* __restrict__ x, const float* __restrict__ w,
                                   __half* __restrict__ oh) {
    int row = blockIdx.x;
    int tid = threadIdx.x;
    if (row == 0 && tid < NEXP) g_cnt[tid] = 0;
    if (row < SEQ && tid >= 192 && tid < 224) {
        int i = tid - 192;
        float inv = powf(10000.0f, -(float)i / 32.0f);
        float ang = (float)row * inv;
        float cs, sn;
        sincosf(ang, &sn, &cs);
        g_cos[row * 32 + i] = cs;
        g_sin[row * 32 + i] = sn;
    }
    const float* xr = x + (size_t)row * HDIM;
    float s = 0.f;
    for (int c = tid; c < HDIM; c += 256) { float v = xr[c]; s += v * v; }
    __shared__ float red[8];
    for (int o = 16; o; o >>= 1) s += __shfl_xor_sync(0xffffffffu, s, o);
    if ((tid & 31) == 0) red[tid >> 5] = s;
    __syncthreads();
    if (tid < 8) {
        float v = red[tid];
        for (int o = 4; o; o >>= 1) v += __shfl_xor_sync(0xffu, v, o);
        if (tid == 0) red[0] = v;
    }
    __syncthreads();
    float scale = rsqrtf(red[0] / (float)HDIM + 1e-6f);
    for (int c = tid; c < HDIM; c += 256)
        oh[(size_t)row * HDIM + c] = __float2half_rn(w[c] * xr[c] * scale);
}

// ================= fused rmsnorm2 + gate + topk + gather =================
__global__ __launch_bounds__(256) void normgate_kernel(
    const float* __restrict__ ln2w, const float* __restrict__ gw)
{
    int t = blockIdx.x;
    int tid = threadIdx.x, lane = tid & 31, wid = tid >> 5;
    __shared__ __align__(16) float xs[HDIM];
    __shared__ float slog[8];
    __shared__ float red[8];
    __shared__ int bi[2], bp[2];

    const float* xr = g_x1 + (size_t)t * HDIM;
    float s = 0.f;
    for (int c = tid; c < HDIM; c += 256) { float v = xr[c]; xs[c] = v; s += v * v; }
    for (int o = 16; o; o >>= 1) s += __shfl_xor_sync(0xffffffffu, s, o);
    if (lane == 0) red[wid] = s;
    __syncthreads();
    if (tid < 8) {
        float v = red[tid];
        for (int o = 4; o; o >>= 1) v += __shfl_xor_sync(0xffu, v, o);
        if (tid == 0) red[0] = v;
    }
    __syncthreads();
    float scale = rsqrtf(red[0] / (float)HDIM + 1e-6f);
    for (int c = tid; c < HDIM; c += 256) xs[c] = ln2w[c] * xs[c] * scale;
    __syncthreads();

    float acc = 0.f;
    for (int j = lane; j < HDIM; j += 32) acc += xs[j] * gw[j * 8 + wid];
    for (int o = 16; o; o >>= 1) acc += __shfl_xor_sync(0xffffffffu, acc, o);
    if (lane == 0) slog[wid] = acc;
    __syncthreads();

    if (tid == 0) {
        float l[8];
#pragma unroll
        for (int e = 0; e < 8; e++) l[e] = slog[e];
        float mx = l[0];
#pragma unroll
        for (int e = 1; e < 8; e++) mx = fmaxf(mx, l[e]);
        float se = 0.f;
#pragma unroll
        for (int e = 0; e < 8; e++) se += expf(l[e] - mx);
        float lse = mx + logf(se);
        g_lse2[t] = lse * lse;
        int i0 = 0; float v0 = l[0];
#pragma unroll
        for (int e = 1; e < 8; e++) if (l[e] > v0) { v0 = l[e]; i0 = e; }
        int i1 = -1; float v1 = -INFINITY;
#pragma unroll
        for (int e = 0; e < 8; e++) if (e != i0 && l[e] > v1) { v1 = l[e]; i1 = e; }
        float w0 = 1.f / (1.f + expf(v1 - v0));
        float w1 = 1.f - w0;
        int p0 = atomicAdd(&g_cnt[i0], 1);
        int p1 = atomicAdd(&g_cnt[i1], 1);
        g_ie[2*t] = i0; g_islot[2*t] = p0; g_iw[2*t] = w0;
        g_ie[2*t+1] = i1; g_islot[2*t+1] = p1; g_iw[2*t+1] = w1;
        bi[0] = i0; bp[0] = p0; bi[1] = i1; bp[1] = p1;
    }
    __syncthreads();

    if (tid < 192) {
        int c4 = tid * 4;
        float4 v = *(float4*)&xs[c4];
        uint2 hv; hv.x = pack2(v.x, v.y); hv.y = pack2(v.z, v.w);
        *(uint2*)(g_xg + ((size_t)bi[0] * T_TOK + bp[0]) * HDIM + c4) = hv;
        *(uint2*)(g_xg + ((size_t)bi[1] * T_TOK + bp[1]) * HDIM + c4) = hv;
    }
}

// combine + (block 0) aux reduction
__global__ void combine_kernel(float* __restrict__ out) {
    int t = blockIdx.x;
    int tid = threadIdx.x;
    if (t == 0) {
        __shared__ float red[6];
        float s = 0.f;
        for (int i = tid; i < T_TOK; i += 192) s += g_lse2[i];
        for (int o = 16; o; o >>= 1) s += __shfl_xor_sync(0xffffffffu, s, o);
        if ((tid & 31) == 0) red[tid >> 5] = s;
        __syncthreads();
        if (tid == 0) {
            float v = 0.f;
            for (int i = 0; i < 6; i++) v += red[i];
            out[(size_t)T_TOK * HDIM] = 0.001f * v / (float)T_TOK;
        }
        __syncthreads();
    }
    int i0 = g_ie[2*t], i1 = g_ie[2*t+1];
    int p0 = g_islot[2*t], p1 = g_islot[2*t+1];
    float w0 = g_iw[2*t], w1 = g_iw[2*t+1];
    const float4* d0 = (const float4*)(g_dg + ((size_t)i0 * T_TOK + p0) * HDIM);
    const float4* d1 = (const float4*)(g_dg + ((size_t)i1 * T_TOK + p1) * HDIM);
    const float4* xr = (const float4*)(g_x1 + (size_t)t * HDIM);
    float4* o = (float4*)(out + (size_t)t * HDIM);
    int c = tid;
    float4 a = xr[c], b0 = d0[c], b1 = d1[c];
    a.x += w0 * b0.x + w1 * b1.x;
    a.y += w0 * b0.y + w1 * b1.y;
    a.z += w0 * b0.z + w1 * b1.z;
    a.w += w0 * b0.w + w1 * b1.w;
    o[c] = a;
}

// ================= tensor-core flash attention (fp16, cp.async 2-stage) ===========
#define FROW 144
#define FTILE 9216
#define FLASH_SMEM (5*FTILE)

__global__ __launch_bounds__(128) void flashmma_kernel() {
    int qt = 31 - (int)blockIdx.x;
    int hh = blockIdx.y, bb = blockIdx.z;
    extern __shared__ char fsm[];
    uint32_t sb = s2u(fsm);
    uint32_t sQ = sb;
    char* pS = fsm;

    int tid = threadIdx.x, lane = tid & 31, w = tid >> 5;
    size_t hb = (size_t)bb * NHEADS + hh;
    const __half* Qp = g_qx + hb * SEQ * HEADD;
    const __half* Kp = g_kx + hb * SEQ * HEADD;
    const __half* Vp = g_vtx + hb * HEADD * SEQ;

#define FLOAD(kt, ss) do { \
    uint32_t _kb = sb + FTILE * (1 + 2 * (ss)); \
    uint32_t _vb = _kb + FTILE; \
    for (int _i = tid; _i < 512; _i += 128) { \
        int _r = _i >> 3, _ch = _i & 7; \
        CP_ASYNC16(_kb + _r * FROW + _ch * 16, Kp + (size_t)((kt) * 64 + _r) * HEADD + _ch * 8); \
        CP_ASYNC16(_vb + _r * FROW + _ch * 16, Vp + (size_t)_r * SEQ + (kt) * 64 + _ch * 8); \
    } \
    asm volatile("cp.async.commit_group;"); \
} while (0)

    FLOAD(0, 0);
    for (int i = tid; i < 512; i += 128) {
        int r = i >> 3, ch = i & 7;
        *(uint4*)(pS + r * FROW + ch * 16) =
            *(const uint4*)(Qp + (size_t)(qt * 64 + r) * HEADD + ch * 8);
    }
    __syncthreads();

    uint32_t qf[4][4];
#pragma unroll
    for (int ks = 0; ks < 4; ks++) {
        uint32_t ao = (uint32_t)(w * 16 + (lane & 15)) * FROW + ks * 32 + (lane >> 4) * 16;
        LDSM4(qf[ks], sQ + ao);
    }

    float accO[8][4];
#pragma unroll
    for (int i = 0; i < 8; i++)
#pragma unroll
        for (int j = 0; j < 4; j++) accO[i][j] = 0.f;
    float mrow0 = -INFINITY, mrow1 = -INFINITY, lrow0 = 0.f, lrow1 = 0.f;
    const float SC = 0.125f * 1.44269504f;

    for (int kt = 0; kt <= qt; kt++) {
        __syncthreads();
        if (kt < qt) {
            FLOAD(kt + 1, (kt + 1) & 1);
            asm volatile("cp.async.wait_group 1;");
        } else {
            asm volatile("cp.async.wait_group 0;");
        }
        __syncthreads();

        uint32_t sK = sb + FTILE * (1 + 2 * (kt & 1));
        uint32_t sV = sK + FTILE;

        float sacc[8][4];
#pragma unroll
        for (int nt = 0; nt < 8; nt++)
#pragma unroll
            for (int j = 0; j < 4; j++) sacc[nt][j] = 0.f;
#pragma unroll
        for (int ks = 0; ks < 4; ks++) {
#pragma unroll
            for (int nt = 0; nt < 8; nt++) {
                uint32_t k2[2];
                uint32_t bo = (uint32_t)(nt * 8 + (lane & 7)) * FROW + ks * 32 + ((lane >> 3) & 1) * 16;
                LDSM2(k2, sK + bo);
                MMA_F16(sacc[nt], qf[ks], k2);
            }
        }

        int grow = qt * 64 + w * 16 + (lane >> 2);
        if (kt == qt) {
#pragma unroll
            for (int nt = 0; nt < 8; nt++) {
                int cbase = kt * 64 + nt * 8 + (lane & 3) * 2;
                sacc[nt][0] = (cbase     <= grow    ) ? sacc[nt][0] * SC : -1e30f;
                sacc[nt][1] = (cbase + 1 <= grow    ) ? sacc[nt][1] * SC : -1e30f;
                sacc[nt][2] = (cbase     <= grow + 8) ? sacc[nt][2] * SC : -1e30f;
                sacc[nt][3] = (cbase + 1 <= grow + 8) ? sacc[nt][3] * SC : -1e30f;
            }
        } else {
#pragma unroll
            for (int nt = 0; nt < 8; nt++)
#pragma unroll
                for (int j = 0; j < 4; j++) sacc[nt][j] *= SC;
        }

        float mx0 = -INFINITY, mx1 = -INFINITY;
#pragma unroll
        for (int nt = 0; nt < 8; nt++) {
            mx0 = fmaxf(mx0, fmaxf(sacc[nt][0], sacc[nt][1]));
            mx1 = fmaxf(mx1, fmaxf(sacc[nt][2], sacc[nt][3]));
        }
        mx0 = fmaxf(mx0, __shfl_xor_sync(0xffffffffu, mx0, 1));
        mx0 = fmaxf(mx0, __shfl_xor_sync(0xffffffffu, mx0, 2));
        mx1 = fmaxf(mx1, __shfl_xor_sync(0xffffffffu, mx1, 1));
        mx1 = fmaxf(mx1, __shfl_xor_sync(0xffffffffu, mx1, 2));
        float mn0 = fmaxf(mrow0, mx0), mn1 = fmaxf(mrow1, mx1);
        float al0 = exp2f(mrow0 - mn0), al1 = exp2f(mrow1 - mn1);
        mrow0 = mn0; mrow1 = mn1;
#pragma unroll
        for (int nt = 0; nt < 8; nt++) {
            accO[nt][0] *= al0; accO[nt][1] *= al0;
            accO[nt][2] *= al1; accO[nt][3] *= al1;
        }
        lrow0 *= al0; lrow1 *= al1;

        float sum0 = 0.f, sum1 = 0.f;
#pragma unroll
        for (int ks = 0; ks < 4; ks++) {
            float p[2][4];
#pragma unroll
            for (int h2 = 0; h2 < 2; h2++) {
                int nt = ks * 2 + h2;
                p[h2][0] = exp2f(sacc[nt][0] - mn0);
                p[h2][1] = exp2f(sacc[nt][1] - mn0);
                p[h2][2] = exp2f(sacc[nt][2] - mn1);
                p[h2][3] = exp2f(sacc[nt][3] - mn1);
                sum0 += p[h2][0] + p[h2][1];
                sum1 += p[h2][2] + p[h2][3];
            }
            uint32_t pf[4];
            pf[0] = pack2(p[0][0], p[0][1]);
            pf[1] = pack2(p[0][2], p[0][3]);
            pf[2] = pack2(p[1][0], p[1][1]);
            pf[3] = pack2(p[1][2], p[1][3]);
#pragma unroll
            for (int ntd = 0; ntd < 8; ntd++) {
                uint32_t v2[2];
                uint32_t vo = (uint32_t)(ntd * 8 + (lane & 7)) * FROW + ks * 32 + ((lane >> 3) & 1) * 16;
                LDSM2(v2, sV + vo);
                MMA_F16(accO[ntd], pf, v2);
            }
        }
        sum0 += __shfl_xor_sync(0xffffffffu, sum0, 1);
        sum0 += __shfl_xor_sync(0xffffffffu, sum0, 2);
        sum1 += __shfl_xor_sync(0xffffffffu, sum1, 1);
        sum1 += __shfl_xor_sync(0xffffffffu, sum1, 2);
        lrow0 += sum0; lrow1 += sum1;
    }

    float inv0 = 1.f / lrow0, inv1 = 1.f / lrow1;
    int row0 = qt * 64 + w * 16 + (lane >> 2);
    size_t rb = ((size_t)bb * SEQ + row0) * HDIM + hh * HEADD + (lane & 3) * 2;
#pragma unroll
    for (int ntd = 0; ntd < 8; ntd++) {
        *(uint32_t*)(g_ox + rb + ntd * 8) = pack2(accO[ntd][0] * inv0, accO[ntd][1] * inv0);
        *(uint32_t*)(g_ox + rb + 8 * HDIM + ntd * 8) = pack2(accO[ntd][2] * inv1, accO[ntd][3] * inv1);
    }
}

// ================= launch =================
#define GSA(var, sym) do { void* _p; cudaGetSymbolAddress(&_p, sym); var = (decltype(var))_p; } while (0)

extern "C" void kernel_launch(void* const* d_in, const int* in_sizes, int n_in,
                              void* d_out, int out_size) {
    const float* hidden = (const float*)d_in[0];
    const float* wq    = (const float*)d_in[2];
    const float* wk    = (const float*)d_in[3];
    const float* wv    = (const float*)d_in[4];
    const float* wo    = (const float*)d_in[5];
    const float* ln1   = (const float*)d_in[6];
    const float* ln2   = (const float*)d_in[7];
    const float* gw    = (const float*)d_in[8];
    const float* wgate = (const float*)d_in[9];
    const float* wup   = (const float*)d_in[10];
    const float* wdown = (const float*)d_in[11];
    float* out = (float*)d_out;

    float *x1, *dg;
    int* cnt;
    __half *ax, *ox, *xg, *hg;
    __half *wqkvp, *wop, *wgup, *wdnp;
    GSA(x1, g_x1); GSA(dg, g_dg); GSA(cnt, g_cnt);
    GSA(ax, g_ax); GSA(ox, g_ox); GSA(xg, g_xg); GSA(hg, g_hg);
    GSA(wqkvp, g_wqkv); GSA(wop, g_wo); GSA(wgup, g_wgu); GSA(wdnp, g_wdn);

    cudaFuncSetAttribute((const void*)tmma_kernel,
                         cudaFuncAttributeMaxDynamicSharedMemorySize, TMMA_SMEM_BIG);
    cudaFuncSetAttribute((const void*)flashmma_kernel,
                         cudaFuncAttributeMaxDynamicSharedMemorySize, FLASH_SMEM);

    // --- side stream + events (created once on first, uncaptured call) ---
    static cudaStream_t s1 = nullptr;
    static cudaEvent_t evFork = nullptr, evWo = nullptr, evWgu = nullptr;
    if (!s1) {
        cudaStream_t tmp = nullptr;
        if (cudaStreamCreateWithFlags(&tmp, cudaStreamNonBlocking) == cudaSuccess && tmp) {
            cudaEventCreateWithFlags(&evFork, cudaEventDisableTiming);
            cudaEventCreateWithFlags(&evWo, cudaEventDisableTiming);
            cudaEventCreateWithFlags(&evWgu, cudaEventDisableTiming);
            s1 = tmp;
        }
    }
    bool fork = (s1 != nullptr);

    if (fork) {
        cudaEventRecord(evFork, 0);
        cudaStreamWaitEvent(s1, evFork, 0);
        wconv_kernel<<<dim3(12, 12, 1), 256, 0, s1>>>(wo, wop, HDIM, HDIM, 0, 0, 0, 0);
        cudaEventRecord(evWo, s1);
        wconv_kernel<<<dim3(32, 12, NEXP), 256, 0, s1>>>(wgate, wgup, HDIM, IDIM,
                                                         (size_t)HDIM*IDIM, (size_t)2*IDIM*HDIM, 1, 0);
        wconv_kernel<<<dim3(32, 12, NEXP), 256, 0, s1>>>(wup, wgup, HDIM, IDIM,
                                                         (size_t)HDIM*IDIM, (size_t)2*IDIM*HDIM, 2, 0);
        wconv_kernel<<<dim3(12, 32, NEXP), 256, 0, s1>>>(wdown, wdnp, IDIM, HDIM,
                                                         (size_t)IDIM*HDIM, (size_t)HDIM*IDIM, 0, 0);
        cudaEventRecord(evWgu, s1);
    } else {
        wconv_kernel<<<dim3(12, 12, 1), 256>>>(wo, wop, HDIM, HDIM, 0, 0, 0, 0);
        wconv_kernel<<<dim3(32, 12, NEXP), 256>>>(wgate, wgup, HDIM, IDIM,
                                                  (size_t)HDIM*IDIM, (size_t)2*IDIM*HDIM, 1, 0);
        wconv_kernel<<<dim3(32, 12, NEXP), 256>>>(wup, wgup, HDIM, IDIM,
                                                  (size_t)HDIM*IDIM, (size_t)2*IDIM*HDIM, 2, 0);
        wconv_kernel<<<dim3(12, 32, NEXP), 256>>>(wdown, wdnp, IDIM, HDIM,
                                                  (size_t)IDIM*HDIM, (size_t)HDIM*IDIM, 0, 0);
    }

    wconv_kernel<<<dim3(12, 12, 1), 256>>>(wq, wqkvp, HDIM, HDIM, 0, 0, 0, 0);
    wconv_kernel<<<dim3(12, 12, 1), 256>>>(wk, wqkvp, HDIM, HDIM, 0, 0, 0, 768);
    wconv_kernel<<<dim3(12, 12, 1), 256>>>(wv, wqkvp, HDIM, HDIM, 0, 0, 0, 1536);

    rmsnorm_f16_kernel<<<T_TOK, 256>>>(hidden, ln1, ax);

    // QKV projection with fused RoPE / V-transpose epilogue
    tmma_kernel<<<dim3(18, 32, 1), 256, TMMA_SMEM_BIG>>>(ax, wqkvp, nullptr,
        T_TOK, nullptr, 2304, HDIM, nullptr, 0, 0, 0, nullptr, 4);

    flashmma_kernel<<<dim3(32, NHEADS, BATCH), 128, FLASH_SMEM>>>();

    if (fork) cudaStreamWaitEvent(0, evWo, 0);
    tmma_kernel<<<dim3(6, 32, 1), 256, TMMA_SMEM_PLAIN>>>(ox, wop, x1,
        T_TOK, nullptr, HDIM, HDIM, hidden, 0, 0, 0, nullptr, 0);

    normgate_kernel<<<T_TOK, 256>>>(ln2, gw);

    if (fork) cudaStreamWaitEvent(0, evWgu, 0);
    tmma_kernel<<<dim3(32, 32, NEXP), 256, TMMA_SMEM_BIG>>>(xg, wgup, nullptr,
        0, cnt, 2 * IDIM, HDIM, nullptr,
        (size_t)T_TOK * HDIM, (size_t)2 * IDIM * HDIM, (size_t)T_TOK * IDIM, hg, 1);
    tmma_kernel<<<dim3(6, 32, NEXP), 256, TMMA_SMEM_PLAIN>>>(hg, wdnp, dg,
        0, cnt, HDIM, IDIM, nullptr,
        (size_t)T_TOK * IDIM, (size_t)HDIM * IDIM, (size_t)T_TOK * HDIM, nullptr, 0);

    combine_kernel<<<T_TOK, 192>>>(out);
}

// round 15
// speedup vs baseline: 1.6048x; 1.0029x over previous
#include <cuda_runtime.h>
#include <cuda_fp16.h>
#include <math.h>
#include <stdint.h>

// ---- problem constants ----
#define T_TOK 4096      // B*S
#define SEQ   2048
#define BATCH 2
#define HDIM  768
#define NHEADS 12
#define HEADD 64
#define IDIM  2048
#define NEXP  8

// ---- fp32 scratch ----
__device__ __align__(128) float g_x1  [T_TOK*HDIM];
__device__ __align__(128) float g_dg  [(size_t)NEXP*T_TOK*HDIM];
__device__ float g_cos [SEQ*32];
__device__ float g_sin [SEQ*32];
__device__ float g_lse2[T_TOK];
__device__ int   g_cnt [NEXP];
__device__ int   g_ie  [2*T_TOK];
__device__ int   g_islot[2*T_TOK];
__device__ float g_iw  [2*T_TOK];

// ---- fp16 activations ----
__device__ __align__(128) __half g_ax  [T_TOK*HDIM];
__device__ __align__(128) __half g_qx  [T_TOK*HDIM];   // [b,h,s,d]
__device__ __align__(128) __half g_kx  [T_TOK*HDIM];
__device__ __align__(128) __half g_vtx [T_TOK*HDIM];   // [b,h,d,s]
__device__ __align__(128) __half g_ox  [T_TOK*HDIM];
__device__ __align__(128) __half g_xg  [(size_t)NEXP*T_TOK*HDIM];
__device__ __align__(128) __half g_hg  [(size_t)NEXP*T_TOK*IDIM];

// ---- fp16 weights ([N,K] K-major; gate/up interleaved 64-row groups) ----
__device__ __align__(128) __half g_wqkv[2304*HDIM];
__device__ __align__(128) __half g_wo  [HDIM*HDIM];
__device__ __align__(128) __half g_wgu [(size_t)NEXP*2*IDIM*HDIM];
__device__ __align__(128) __half g_wdn [(size_t)NEXP*HDIM*IDIM];

// ================= helpers =================
__device__ __forceinline__ uint32_t s2u(const void* p) {
    uint32_t a;
    asm("{ .reg .u64 t; cvta.to.shared.u64 t, %1; cvt.u32.u64 %0, t; }" : "=r"(a) : "l"(p));
    return a;
}
__device__ __forceinline__ uint32_t pack2(float a, float b) {
    __half2 h2 = __halves2half2(__float2half_rn(a), __float2half_rn(b));
    return *(uint32_t*)&h2;
}

#define LDSM4(r, a) \
    asm volatile("ldmatrix.sync.aligned.m8n8.x4.shared.b16 {%0,%1,%2,%3}, [%4];" \
        : "=r"((r)[0]), "=r"((r)[1]), "=r"((r)[2]), "=r"((r)[3]) : "r"(a))
#define LDSM2(r, a) \
    asm volatile("ldmatrix.sync.aligned.m8n8.x2.shared.b16 {%0,%1}, [%2];" \
        : "=r"((r)[0]), "=r"((r)[1]) : "r"(a))
#define MMA_F16(c, a, b) \
    asm volatile("mma.sync.aligned.m16n8k16.row.col.f32.f16.f16.f32 " \
        "{%0,%1,%2,%3}, {%4,%5,%6,%7}, {%8,%9}, {%0,%1,%2,%3};" \
        : "+f"((c)[0]), "+f"((c)[1]), "+f"((c)[2]), "+f"((c)[3]) \
        : "r"((a)[0]), "r"((a)[1]), "r"((a)[2]), "r"((a)[3]), "r"((b)[0]), "r"((b)[1]))
#define CP_ASYNC16(dst, src) \
    asm volatile("cp.async.cg.shared.global [%0], [%1], 16;" :: "r"(dst), "l"(src))

// ================= weight transpose + fp16 round =================
__global__ __launch_bounds__(256) void wconv_kernel(
    const float* __restrict__ W, __half* __restrict__ oh, int K, int N,
    size_t inZ, size_t outZ, int mode, int dstOff)
{
    W  += (size_t)blockIdx.z * inZ;
    oh += (size_t)blockIdx.z * outZ;
    __shared__ float s[64][65];
    int n0 = blockIdx.x * 64, k0 = blockIdx.y * 64;
    int tid = threadIdx.x;
    int lr = tid >> 4;
    int lc = (tid & 15) * 4;
#pragma unroll
    for (int p = 0; p < 4; p++) {
        int kk = p * 16 + lr;
        float4 v = *(const float4*)(W + (size_t)(k0 + kk) * N + n0 + lc);
        s[lc + 0][kk] = v.x; s[lc + 1][kk] = v.y;
        s[lc + 2][kk] = v.z; s[lc + 3][kk] = v.w;
    }
    __syncthreads();
    int nl = tid >> 3;
    int kq = (tid & 7) * 8;
#pragma unroll
    for (int p = 0; p < 2; p++) {
        int nn = p * 32 + nl;
        int ng = n0 + nn;
        int nd = (mode == 0) ? ng : ((ng >> 6) * 128 + (ng & 63) + ((mode == 2) ? 64 : 0));
        nd += dstOff;
        __half hb[8];
#pragma unroll
        for (int j = 0; j < 8; j++) hb[j] = __float2half_rn(s[nn][kq + j]);
        *(uint4*)(oh + (size_t)nd * K + k0 + kq) = *(uint4*)hb;
    }
}

// ================= mma.sync fp16 GEMM (batched) =================
// outMode: 0 = fp32 C (+Cadd), 1 = fused silu -> fp16 SO, 4 = fused RoPE/V-transpose (QKV)
#define TMMA_SMEM_PLAIN 61440
#define TMMA_SMEM_BIG   67584

__global__ __launch_bounds__(256) void tmma_kernel(
    const __half* __restrict__ A, const __half* __restrict__ B,
    float* __restrict__ C, int M, const int* __restrict__ cntArr,
    int N, int K, const float* __restrict__ Cadd,
    size_t zsA, size_t zsB, size_t zsC,
    __half* __restrict__ SO, int outMode)
{
    int z = blockIdx.z;
    int m = cntArr ? cntArr[z] : M;
    int row0 = blockIdx.y * 128;
    if (row0 >= m) return;
    int col0 = blockIdx.x * 128;
    A += zsA * z; B += zsB * z;
    if (outMode == 0) C += zsC * z; else if (outMode == 1) SO += zsC * z;

    extern __shared__ char sm[];
    uint32_t sbase = s2u(sm);
    int tid = threadIdx.x, lane = tid & 31, wid = tid >> 5;
    int wm = wid & 1, wn = wid >> 1;

    const __half* sp[2];
    sp[0] = A + (size_t)row0 * K;
    sp[1] = B + (size_t)col0 * K;

    float acc[4][4][4];
#pragma unroll
    for (int a = 0; a < 4; a++)
#pragma unroll
        for (int b = 0; b < 4; b++)
#pragma unroll
            for (int c = 0; c < 4; c++) acc[a][b][c] = 0.f;

    int NC = K >> 5;

#define LOAD_STAGE(cc, ss) do { \
    uint32_t _db = sbase + (ss) * 20480; \
    _Pragma("unroll") \
    for (int _t = 0; _t < 2; _t++) { \
        _Pragma("unroll") \
        for (int _i = 0; _i < 2; _i++) { \
            int _idx = tid + _i * 256; \
            int _r = _idx >> 2, _ch = _idx & 3; \
            uint32_t _dst = _db + _t * 10240 + _r * 80 + _ch * 16; \
            const void* _src = sp[_t] + (size_t)_r * K + (cc) * 32 + _ch * 8; \
            CP_ASYNC16(_dst, _src); \
        } \
    } \
    asm volatile("cp.async.commit_group;"); \
} while (0)

    LOAD_STAGE(0, 0);
    if (NC > 1) LOAD_STAGE(1, 1);

    int st = 0;
    for (int c = 0; c < NC; c++) {
        if (c + 2 < NC) {
            int s2 = st + 2; if (s2 >= 3) s2 -= 3;
            LOAD_STAGE(c + 2, s2);
            asm volatile("cp.async.wait_group 2;");
        } else if (c + 1 < NC) {
            asm volatile("cp.async.wait_group 1;");
        } else {
            asm volatile("cp.async.wait_group 0;");
        }
        __syncthreads();

        uint32_t db = sbase + st * 20480;
        uint32_t aT = db, bT = db + 10240;
#pragma unroll
        for (int ks = 0; ks < 2; ks++) {
            uint32_t af[4][4], bf[4][2];
            uint32_t aoff = (uint32_t)(wm * 64 + (lane & 15)) * 80 + ks * 32 + (lane >> 4) * 16;
            uint32_t boff = (uint32_t)(wn * 32 + (lane & 7)) * 80 + ks * 32 + ((lane >> 3) & 1) * 16;
#pragma unroll
            for (int mt = 0; mt < 4; mt++)
                LDSM4(af[mt], aT + aoff + mt * 1280);
#pragma unroll
            for (int nt = 0; nt < 4; nt++)
                LDSM2(bf[nt], bT + boff + nt * 640);
#pragma unroll
            for (int mt = 0; mt < 4; mt++)
#pragma unroll
                for (int nt = 0; nt < 4; nt++)
                    MMA_F16(acc[mt][nt], af[mt], bf[nt]);
        }
        __syncthreads();
        if (++st == 3) st = 0;
    }

    if (outMode == 1 || outMode == 4) {
        float* stg = (float*)sm;   // 128 x 132 floats
#pragma unroll
        for (int mt = 0; mt < 4; mt++) {
            int r = wm * 64 + mt * 16 + (lane >> 2);
            int cbase = wn * 32 + (lane & 3) * 2;
#pragma unroll
            for (int half = 0; half < 2; half++) {
#pragma unroll
                for (int nt = 0; nt < 4; nt++) {
                    float2 v; v.x = acc[mt][nt][half * 2 + 0]; v.y = acc[mt][nt][half * 2 + 1];
                    *(float2*)&stg[(r + half * 8) * 132 + cbase + nt * 8] = v;
                }
            }
        }
        __syncthreads();

        if (outMode == 1) {
            int lr = tid >> 4;
            int lc = (tid & 15) * 4;
            int colg = blockIdx.x * 64 + lc;
#pragma unroll
            for (int p = 0; p < 8; p++) {
                int r = p * 16 + lr;
                int gr = row0 + r;
                if (gr < m) {
                    float4 gv = *(float4*)&stg[r * 132 + lc];
                    float4 uv = *(float4*)&stg[r * 132 + 64 + lc];
                    float f0 = gv.x / (1.f + expf(-gv.x)) * uv.x;
                    float f1 = gv.y / (1.f + expf(-gv.y)) * uv.y;
                    float f2 = gv.z / (1.f + expf(-gv.z)) * uv.z;
                    float f3 = gv.w / (1.f + expf(-gv.w)) * uv.w;
                    uint2 hv; hv.x = pack2(f0, f1); hv.y = pack2(f2, f3);
                    *(uint2*)(SO + (size_t)gr * IDIM + colg) = hv;
                }
            }
            return;
        }

        // outMode 4: fused RoPE (q/k) / transpose (v). Tile is fully inside one part.
        int part = col0 / 768;     // 0=q, 1=k, 2=v
        if (part < 2) {
            __half* dstp = (part == 0) ? g_qx : g_kx;
            int base = col0 - part * 768;
#pragma unroll
            for (int i = 0; i < 64; i++) {
                int idx = tid + i * 256;
                int cc = idx & 127, r = idx >> 7;
                int gr = row0 + r;
                int gc = base + cc;
                int h = gc >> 6, d = gc & 63;
                int bb = gr >> 11, s = gr & 2047;
                float v = stg[r * 132 + cc];
                int pairc = cc + ((d < 32) ? 32 : -32);
                float pv = stg[r * 132 + pairc];
                float cs = g_cos[s * 32 + (d & 31)];
                float sn = g_sin[s * 32 + (d & 31)];
                float sgn = (d < 32) ? -1.f : 1.f;
                float rot = v * cs + sgn * pv * sn;
                dstp[(((size_t)bb * NHEADS + h) * SEQ + s) * HEADD + d] = __float2half_rn(rot);
            }
        } else {
            int base = col0 - 1536;
#pragma unroll
            for (int i = 0; i < 64; i++) {
                int idx = tid + i * 256;
                int r = idx & 127, cc = idx >> 7;
                int gr = row0 + r;
                int gc = base + cc;
                int h = gc >> 6, d = gc & 63;
                int bb = gr >> 11, s = gr & 2047;
                g_vtx[(((size_t)bb * NHEADS + h) * HEADD + d) * SEQ + s] =
                    __float2half_rn(stg[r * 132 + cc]);
            }
        }
        return;
    }

#pragma unroll
    for (int mt = 0; mt < 4; mt++) {
        int rbase = row0 + wm * 64 + mt * 16 + (lane >> 2);
#pragma unroll
        for (int half = 0; half < 2; half++) {
            int rr = rbase + half * 8;
            if (rr < m) {
                size_t o = (size_t)rr * N + col0 + wn * 32 + (lane & 3) * 2;
#pragma unroll
                for (int nt = 0; nt < 4; nt++) {
                    float v0 = acc[mt][nt][half * 2 + 0];
                    float v1 = acc[mt][nt][half * 2 + 1];
                    size_t oo = o + nt * 8;
                    if (Cadd) {
                        float2 ad = *(const float2*)(Cadd + oo);
                        v0 += ad.x; v1 += ad.y;
                    }
                    float2 st2; st2.x = v0; st2.y = v1;
                    *(float2*)(C + oo) = st2;
                }
            }
        }
    }
}

// ================= RMSNorm (pre-attention) + rope table fill =================
__global__ void rmsnorm_f16_kernel(const float* __restrict__ x, const float* __restrict__ w,
                                   __half* __restrict__ oh) {
    int row = blockIdx.x;
    int tid = threadIdx.x;
    if (row == 0 && tid < NEXP) g_cnt[tid] = 0;
    if (row < SEQ && tid >= 192 && tid < 224) {
        int i = tid - 192;
        float inv = powf(10000.0f, -(float)i / 32.0f);
        float ang = (float)row * inv;
        float cs, sn;
        sincosf(ang, &sn, &cs);
        g_cos[row * 32 + i] = cs;
        g_sin[row * 32 + i] = sn;
    }
    const float* xr = x + (size_t)row * HDIM;
    float s = 0.f;
    for (int c = tid; c < HDIM; c += 256) { float v = xr[c]; s += v * v; }
    __shared__ float red[8];
    for (int o = 16; o; o >>= 1) s += __shfl_xor_sync(0xffffffffu, s, o);
    if ((tid & 31) == 0) red[tid >> 5] = s;
    __syncthreads();
    if (tid < 8) {
        float v = red[tid];
        for (int o = 4; o; o >>= 1) v += __shfl_xor_sync(0xffu, v, o);
        if (tid == 0) red[0] = v;
    }
    __syncthreads();
    float scale = rsqrtf(red[0] / (float)HDIM + 1e-6f);
    for (int c = tid; c < HDIM; c += 256)
        oh[(size_t)row * HDIM + c] = __float2half_rn(w[c] * xr[c] * scale);
}

// ================= fused rmsnorm2 + gate + topk + gather =================
__global__ __launch_bounds__(256) void normgate_kernel(
    const float* __restrict__ ln2w, const float* __restrict__ gw)
{
    int t = blockIdx.x;
    int tid = threadIdx.x, lane = tid & 31, wid = tid >> 5;
    __shared__ __align__(16) float xs[HDIM];
    __shared__ float slog[8];
    __shared__ float red[8];
    __shared__ int bi[2], bp[2];

    const float* xr = g_x1 + (size_t)t * HDIM;
    float s = 0.f;
    for (int c = tid; c < HDIM; c += 256) { float v = xr[c]; xs[c] = v; s += v * v; }
    for (int o = 16; o; o >>= 1) s += __shfl_xor_sync(0xffffffffu, s, o);
    if (lane == 0) red[wid] = s;
    __syncthreads();
    if (tid < 8) {
        float v = red[tid];
        for (int o = 4; o; o >>= 1) v += __shfl_xor_sync(0xffu, v, o);
        if (tid == 0) red[0] = v;
    }
    __syncthreads();
    float scale = rsqrtf(red[0] / (float)HDIM + 1e-6f);
    for (int c = tid; c < HDIM; c += 256) xs[c] = ln2w[c] * xs[c] * scale;
    __syncthreads();

    float acc = 0.f;
    for (int j = lane; j < HDIM; j += 32) acc += xs[j] * gw[j * 8 + wid];
    for (int o = 16; o; o >>= 1) acc += __shfl_xor_sync(0xffffffffu, acc, o);
    if (lane == 0) slog[wid] = acc;
    __syncthreads();

    if (tid == 0) {
        float l[8];
#pragma unroll
        for (int e = 0; e < 8; e++) l[e] = slog[e];
        float mx = l[0];
#pragma unroll
        for (int e = 1; e < 8; e++) mx = fmaxf(mx, l[e]);
        float se = 0.f;
#pragma unroll
        for (int e = 0; e < 8; e++) se += expf(l[e] - mx);
        float lse = mx + logf(se);
        g_lse2[t] = lse * lse;
        int i0 = 0; float v0 = l[0];
#pragma unroll
        for (int e = 1; e < 8; e++) if (l[e] > v0) { v0 = l[e]; i0 = e; }
        int i1 = -1; float v1 = -INFINITY;
#pragma unroll
        for (int e = 0; e < 8; e++) if (e != i0 && l[e] > v1) { v1 = l[e]; i1 = e; }
        float w0 = 1.f / (1.f + expf(v1 - v0));
        float w1 = 1.f - w0;
        int p0 = atomicAdd(&g_cnt[i0], 1);
        int p1 = atomicAdd(&g_cnt[i1], 1);
        g_ie[2*t] = i0; g_islot[2*t] = p0; g_iw[2*t] = w0;
        g_ie[2*t+1] = i1; g_islot[2*t+1] = p1; g_iw[2*t+1] = w1;
        bi[0] = i0; bp[0] = p0; bi[1] = i1; bp[1] = p1;
    }
    __syncthreads();

    if (tid < 192) {
        int c4 = tid * 4;
        float4 v = *(float4*)&xs[c4];
        uint2 hv; hv.x = pack2(v.x, v.y); hv.y = pack2(v.z, v.w);
        *(uint2*)(g_xg + ((size_t)bi[0] * T_TOK + bp[0]) * HDIM + c4) = hv;
        *(uint2*)(g_xg + ((size_t)bi[1] * T_TOK + bp[1]) * HDIM + c4) = hv;
    }
}

// combine + (block 0) aux reduction
__global__ void combine_kernel(float* __restrict__ out) {
    int t = blockIdx.x;
    int tid = threadIdx.x;
    if (t == 0) {
        __shared__ float red[6];
        float s = 0.f;
        for (int i = tid; i < T_TOK; i += 192) s += g_lse2[i];
        for (int o = 16; o; o >>= 1) s += __shfl_xor_sync(0xffffffffu, s, o);
        if ((tid & 31) == 0) red[tid >> 5] = s;
        __syncthreads();
        if (tid == 0) {
            float v = 0.f;
            for (int i = 0; i < 6; i++) v += red[i];
            out[(size_t)T_TOK * HDIM] = 0.001f * v / (float)T_TOK;
        }
        __syncthreads();
    }
    int i0 = g_ie[2*t], i1 = g_ie[2*t+1];
    int p0 = g_islot[2*t], p1 = g_islot[2*t+1];
    float w0 = g_iw[2*t], w1 = g_iw[2*t+1];
    const float4* d0 = (const float4*)(g_dg + ((size_t)i0 * T_TOK + p0) * HDIM);
    const float4* d1 = (const float4*)(g_dg + ((size_t)i1 * T_TOK + p1) * HDIM);
    const float4* xr = (const float4*)(g_x1 + (size_t)t * HDIM);
    float4* o = (float4*)(out + (size_t)t * HDIM);
    int c = tid;
    float4 a = xr[c], b0 = d0[c], b1 = d1[c];
    a.x += w0 * b0.x + w1 * b1.x;
    a.y += w0 * b0.y + w1 * b1.y;
    a.z += w0 * b0.z + w1 * b1.z;
    a.w += w0 * b0.w + w1 * b1.w;
    o[c] = a;
}

// ================= tensor-core flash attention (fp16, 128-row Q tiles) ===========
#define FROW 144
#define FTILE 9216
#define FLASH_SMEM (6*FTILE)

__global__ __launch_bounds__(256) void flashmma_kernel() {
    int qt = 15 - (int)blockIdx.x;      // heavy tiles first
    int hh = blockIdx.y, bb = blockIdx.z;
    extern __shared__ char fsm[];
    uint32_t sb = s2u(fsm);
    uint32_t sQ = sb;                   // 128 rows = 2*FTILE
    char* pS = fsm;

    int tid = threadIdx.x, lane = tid & 31, w = tid >> 5;   // 8 warps, 16 q-rows each
    size_t hb = (size_t)bb * NHEADS + hh;
    const __half* Qp = g_qx + hb * SEQ * HEADD;
    const __half* Kp = g_kx + hb * SEQ * HEADD;
    const __half* Vp = g_vtx + hb * HEADD * SEQ;

#define FLOAD(kt, ss) do { \
    uint32_t _kb = sb + FTILE * (2 + 2 * (ss)); \
    uint32_t _vb = _kb + FTILE; \
    for (int _i = tid; _i < 512; _i += 256) { \
        int _r = _i >> 3, _ch = _i & 7; \
        CP_ASYNC16(_kb + _r * FROW + _ch * 16, Kp + (size_t)((kt) * 64 + _r) * HEADD + _ch * 8); \
        CP_ASYNC16(_vb + _r * FROW + _ch * 16, Vp + (size_t)_r * SEQ + (kt) * 64 + _ch * 8); \
    } \
    asm volatile("cp.async.commit_group;"); \
} while (0)

    FLOAD(0, 0);
    for (int i = tid; i < 1024; i += 256) {
        int r = i >> 3, ch = i & 7;
        *(uint4*)(pS + r * FROW + ch * 16) =
            *(const uint4*)(Qp + (size_t)(qt * 128 + r) * HEADD + ch * 8);
    }
    __syncthreads();

    uint32_t qf[4][4];
#pragma unroll
    for (int ks = 0; ks < 4; ks++) {
        uint32_t ao = (uint32_t)(w * 16 + (lane & 15)) * FROW + ks * 32 + (lane >> 4) * 16;
        LDSM4(qf[ks], sQ + ao);
    }

    float accO[8][4];
#pragma unroll
    for (int i = 0; i < 8; i++)
#pragma unroll
        for (int j = 0; j < 4; j++) accO[i][j] = 0.f;
    float mrow0 = -INFINITY, mrow1 = -INFINITY, lrow0 = 0.f, lrow1 = 0.f;
    const float SC = 0.125f * 1.44269504f;
    int kmax = 2 * qt + 1;

    for (int kt = 0; kt <= kmax; kt++) {
        __syncthreads();
        if (kt < kmax) {
            FLOAD(kt + 1, (kt + 1) & 1);
            asm volatile("cp.async.wait_group 1;");
        } else {
            asm volatile("cp.async.wait_group 0;");
        }
        __syncthreads();

        uint32_t sK = sb + FTILE * (2 + 2 * (kt & 1));
        uint32_t sV = sK + FTILE;

        float sacc[8][4];
#pragma unroll
        for (int nt = 0; nt < 8; nt++)
#pragma unroll
            for (int j = 0; j < 4; j++) sacc[nt][j] = 0.f;
#pragma unroll
        for (int ks = 0; ks < 4; ks++) {
#pragma unroll
            for (int nt = 0; nt < 8; nt++) {
                uint32_t k2[2];
                uint32_t bo = (uint32_t)(nt * 8 + (lane & 7)) * FROW + ks * 32 + ((lane >> 3) & 1) * 16;
                LDSM2(k2, sK + bo);
                MMA_F16(sacc[nt], qf[ks], k2);
            }
        }

        int grow = qt * 128 + w * 16 + (lane >> 2);
        if (kt >= 2 * qt) {
#pragma unroll
            for (int nt = 0; nt < 8; nt++) {
                int cbase = kt * 64 + nt * 8 + (lane & 3) * 2;
                sacc[nt][0] = (cbase     <= grow    ) ? sacc[nt][0] * SC : -1e30f;
                sacc[nt][1] = (cbase + 1 <= grow    ) ? sacc[nt][1] * SC : -1e30f;
                sacc[nt][2] = (cbase     <= grow + 8) ? sacc[nt][2] * SC : -1e30f;
                sacc[nt][3] = (cbase + 1 <= grow + 8) ? sacc[nt][3] * SC : -1e30f;
            }
        } else {
#pragma unroll
            for (int nt = 0; nt < 8; nt++)
#pragma unroll
                for (int j = 0; j < 4; j++) sacc[nt][j] *= SC;
        }

        float mx0 = -INFINITY, mx1 = -INFINITY;
#pragma unroll
        for (int nt = 0; nt < 8; nt++) {
            mx0 = fmaxf(mx0, fmaxf(sacc[nt][0], sacc[nt][1]));
            mx1 = fmaxf(mx1, fmaxf(sacc[nt][2], sacc[nt][3]));
        }
        mx0 = fmaxf(mx0, __shfl_xor_sync(0xffffffffu, mx0, 1));
        mx0 = fmaxf(mx0, __shfl_xor_sync(0xffffffffu, mx0, 2));
        mx1 = fmaxf(mx1, __shfl_xor_sync(0xffffffffu, mx1, 1));
        mx1 = fmaxf(mx1, __shfl_xor_sync(0xffffffffu, mx1, 2));
        float mn0 = fmaxf(mrow0, mx0), mn1 = fmaxf(mrow1, mx1);
        float al0 = exp2f(mrow0 - mn0), al1 = exp2f(mrow1 - mn1);
        mrow0 = mn0; mrow1 = mn1;
#pragma unroll
        for (int nt = 0; nt < 8; nt++) {
            accO[nt][0] *= al0; accO[nt][1] *= al0;
            accO[nt][2] *= al1; accO[nt][3] *= al1;
        }
        lrow0 *= al0; lrow1 *= al1;

        float sum0 = 0.f, sum1 = 0.f;
#pragma unroll
        for (int ks = 0; ks < 4; ks++) {
            float p[2][4];
#pragma unroll
            for (int h2 = 0; h2 < 2; h2++) {
                int nt = ks * 2 + h2;
                p[h2][0] = exp2f(sacc[nt][0] - mn0);
                p[h2][1] = exp2f(sacc[nt][1] - mn0);
                p[h2][2] = exp2f(sacc[nt][2] - mn1);
                p[h2][3] = exp2f(sacc[nt][3] - mn1);
                sum0 += p[h2][0] + p[h2][1];
                sum1 += p[h2][2] + p[h2][3];
            }
            uint32_t pf[4];
            pf[0] = pack2(p[0][0], p[0][1]);
            pf[1] = pack2(p[0][2], p[0][3]);
            pf[2] = pack2(p[1][0], p[1][1]);
            pf[3] = pack2(p[1][2], p[1][3]);
#pragma unroll
            for (int ntd = 0; ntd < 8; ntd++) {
                uint32_t v2[2];
                uint32_t vo = (uint32_t)(ntd * 8 + (lane & 7)) * FROW + ks * 32 + ((lane >> 3) & 1) * 16;
                LDSM2(v2, sV + vo);
                MMA_F16(accO[ntd], pf, v2);
            }
        }
        sum0 += __shfl_xor_sync(0xffffffffu, sum0, 1);
        sum0 += __shfl_xor_sync(0xffffffffu, sum0, 2);
        sum1 += __shfl_xor_sync(0xffffffffu, sum1, 1);
        sum1 += __shfl_xor_sync(0xffffffffu, sum1, 2);
        lrow0 += sum0; lrow1 += sum1;
    }

    float inv0 = 1.f / lrow0, inv1 = 1.f / lrow1;
    int row0 = qt * 128 + w * 16 + (lane >> 2);
    size_t rb = ((size_t)bb * SEQ + row0) * HDIM + hh * HEADD + (lane & 3) * 2;
#pragma unroll
    for (int ntd = 0; ntd < 8; ntd++) {
        *(uint32_t*)(g_ox + rb + ntd * 8) = pack2(accO[ntd][0] * inv0, accO[ntd][1] * inv0);
        *(uint32_t*)(g_ox + rb + 8 * HDIM + ntd * 8) = pack2(accO[ntd][2] * inv1, accO[ntd][3] * inv1);
    }
}

// ================= launch =================
#define GSA(var, sym) do { void* _p; cudaGetSymbolAddress(&_p, sym); var = (decltype(var))_p; } while (0)

extern "C" void kernel_launch(void* const* d_in, const int* in_sizes, int n_in,
                              void* d_out, int out_size) {
    const float* hidden = (const float*)d_in[0];
    const float* wq    = (const float*)d_in[2];
    const float* wk    = (const float*)d_in[3];
    const float* wv    = (const float*)d_in[4];
    const float* wo    = (const float*)d_in[5];
    const float* ln1   = (const float*)d_in[6];
    const float* ln2   = (const float*)d_in[7];
    const float* gw    = (const float*)d_in[8];
    const float* wgate = (const float*)d_in[9];
    const float* wup   = (const float*)d_in[10];
    const float* wdown = (const float*)d_in[11];
    float* out = (float*)d_out;

    float *x1, *dg;
    int* cnt;
    __half *ax, *ox, *xg, *hg;
    __half *wqkvp, *wop, *wgup, *wdnp;
    GSA(x1, g_x1); GSA(dg, g_dg); GSA(cnt, g_cnt);
    GSA(ax, g_ax); GSA(ox, g_ox); GSA(xg, g_xg); GSA(hg, g_hg);
    GSA(wqkvp, g_wqkv); GSA(wop, g_wo); GSA(wgup, g_wgu); GSA(wdnp, g_wdn);

    cudaFuncSetAttribute((const void*)tmma_kernel,
                         cudaFuncAttributeMaxDynamicSharedMemorySize, TMMA_SMEM_BIG);
    cudaFuncSetAttribute((const void*)flashmma_kernel,
                         cudaFuncAttributeMaxDynamicSharedMemorySize, FLASH_SMEM);

    // --- side stream + events (created once on first, uncaptured call) ---
    static cudaStream_t s1 = nullptr;
    static cudaEvent_t evFork = nullptr, evWo = nullptr, evNG = nullptr, evMoE = nullptr;
    if (!s1) {
        cudaStream_t tmp = nullptr;
        if (cudaStreamCreateWithFlags(&tmp, cudaStreamNonBlocking) == cudaSuccess && tmp) {
            cudaEventCreateWithFlags(&evFork, cudaEventDisableTiming);
            cudaEventCreateWithFlags(&evWo, cudaEventDisableTiming);
            cudaEventCreateWithFlags(&evNG, cudaEventDisableTiming);
            cudaEventCreateWithFlags(&evMoE, cudaEventDisableTiming);
            s1 = tmp;
        }
    }
    bool fork = (s1 != nullptr);

    size_t zsXG = (size_t)T_TOK * HDIM;
    size_t zsWGU = (size_t)2 * IDIM * HDIM;
    size_t zsHG = (size_t)T_TOK * IDIM;
    size_t zsWDN = (size_t)HDIM * IDIM;
    size_t zsDG = (size_t)T_TOK * HDIM;

    if (fork) {
        cudaEventRecord(evFork, 0);
        cudaStreamWaitEvent(s1, evFork, 0);
        wconv_kernel<<<dim3(12, 12, 1), 256, 0, s1>>>(wo, wop, HDIM, HDIM, 0, 0, 0, 0);
        cudaEventRecord(evWo, s1);
        wconv_kernel<<<dim3(32, 12, NEXP), 256, 0, s1>>>(wgate, wgup, HDIM, IDIM,
                                                         (size_t)HDIM*IDIM, zsWGU, 1, 0);
        wconv_kernel<<<dim3(32, 12, NEXP), 256, 0, s1>>>(wup, wgup, HDIM, IDIM,
                                                         (size_t)HDIM*IDIM, zsWGU, 2, 0);
        wconv_kernel<<<dim3(12, 32, NEXP), 256, 0, s1>>>(wdown, wdnp, IDIM, HDIM,
                                                         (size_t)IDIM*HDIM, zsWDN, 0, 0);
    } else {
        wconv_kernel<<<dim3(12, 12, 1), 256>>>(wo, wop, HDIM, HDIM, 0, 0, 0, 0);
        wconv_kernel<<<dim3(32, 12, NEXP), 256>>>(wgate, wgup, HDIM, IDIM,
                                                  (size_t)HDIM*IDIM, zsWGU, 1, 0);
        wconv_kernel<<<dim3(32, 12, NEXP), 256>>>(wup, wgup, HDIM, IDIM,
                                                  (size_t)HDIM*IDIM, zsWGU, 2, 0);
        wconv_kernel<<<dim3(12, 32, NEXP), 256>>>(wdown, wdnp, IDIM, HDIM,
                                                  (size_t)IDIM*HDIM, zsWDN, 0, 0);
    }

    wconv_kernel<<<dim3(12, 12, 1), 256>>>(wq, wqkvp, HDIM, HDIM, 0, 0, 0, 0);
    wconv_kernel<<<dim3(12, 12, 1), 256>>>(wk, wqkvp, HDIM, HDIM, 0, 0, 0, 768);
    wconv_kernel<<<dim3(12, 12, 1), 256>>>(wv, wqkvp, HDIM, HDIM, 0, 0, 0, 1536);

    rmsnorm_f16_kernel<<<T_TOK, 256>>>(hidden, ln1, ax);

    // QKV projection with fused RoPE / V-transpose epilogue
    tmma_kernel<<<dim3(18, 32, 1), 256, TMMA_SMEM_BIG>>>(ax, wqkvp, nullptr,
        T_TOK, nullptr, 2304, HDIM, nullptr, 0, 0, 0, nullptr, 4);

    flashmma_kernel<<<dim3(16, NHEADS, BATCH), 256, FLASH_SMEM>>>();

    if (fork) cudaStreamWaitEvent(0, evWo, 0);
    tmma_kernel<<<dim3(6, 32, 1), 256, TMMA_SMEM_PLAIN>>>(ox, wop, x1,
        T_TOK, nullptr, HDIM, HDIM, hidden, 0, 0, 0, nullptr, 0);

    normgate_kernel<<<T_TOK, 256>>>(ln2, gw);

    if (fork) {
        // split experts: 0-3 on main, 4-7 on s1 (s1 already ordered after its wconv's)
        cudaEventRecord(evNG, 0);
        cudaStreamWaitEvent(s1, evNG, 0);
        tmma_kernel<<<dim3(32, 32, 4), 256, TMMA_SMEM_BIG, s1>>>(
            xg + 4 * zsXG, wgup + 4 * zsWGU, nullptr,
            0, cnt + 4, 2 * IDIM, HDIM, nullptr, zsXG, zsWGU, zsHG, hg + 4 * zsHG, 1);
        tmma_kernel<<<dim3(6, 32, 4), 256, TMMA_SMEM_PLAIN, s1>>>(
            hg + 4 * zsHG, wdnp + 4 * zsWDN, dg + 4 * zsDG,
            0, cnt + 4, HDIM, IDIM, nullptr, zsHG, zsWDN, zsDG, nullptr, 0);
        cudaEventRecord(evMoE, s1);

        tmma_kernel<<<dim3(32, 32, 4), 256, TMMA_SMEM_BIG>>>(xg, wgup, nullptr,
            0, cnt, 2 * IDIM, HDIM, nullptr, zsXG, zsWGU, zsHG, hg, 1);
        tmma_kernel<<<dim3(6, 32, 4), 256, TMMA_SMEM_PLAIN>>>(hg, wdnp, dg,
            0, cnt, HDIM, IDIM, nullptr, zsHG, zsWDN, zsDG, nullptr, 0);

        cudaStreamWaitEvent(0, evMoE, 0);
    } else {
        tmma_kernel<<<dim3(32, 32, NEXP), 256, TMMA_SMEM_BIG>>>(xg, wgup, nullptr,
            0, cnt, 2 * IDIM, HDIM, nullptr, zsXG, zsWGU, zsHG, hg, 1);
        tmma_kernel<<<dim3(6, 32, NEXP), 256, TMMA_SMEM_PLAIN>>>(hg, wdnp, dg,
            0, cnt, HDIM, IDIM, nullptr, zsHG, zsWDN, zsDG, nullptr, 0);
    }

    combine_kernel<<<T_TOK, 192>>>(out);
}